// round 10
// baseline (speedup 1.0000x reference)
#include <cuda_runtime.h>
#include <mma.h>
#include <cstdint>
#include <cstddef>

// tcgen05 is arch-SPECIFIC: only on the sm_103a pass; plain compute_103 gets a fallback.
#if defined(__CUDA_ARCH__) && (defined(__CUDA_ARCH_FEAT_SM103_ALL) || defined(__CUDA_ARCH_FEAT_SM100_ALL) || defined(__CUDA_ARCH_FEAT_SM101_ALL))
#define HAS_TC 1
#else
#define HAS_TC 0
#endif

// Problem constants
#define NBATCH   2
#define CH       64
#define NPTS     262144
#define NBLK     2

// Tiling
#define TILE     224
#define R_IN     230
#define R_B1     228
#define R_B2     226
#define NTHREADS 512
#define GRID_X   ((NPTS + TILE - 1) / TILE)   // 1171
#define NWORK    (GRID_X * NBATCH)            // 2342

// SMEM byte offsets. Activation buffers canonical K-major: addr = c*ROWS*16 + r*16.
#define OFF_IN0   0
#define OFF_IN1   (R_IN * 256)                  // 58880
#define OFF_B1    (OFF_IN1 + R_IN * 256)        // 117760
#define OFF_W     (OFF_B1 + R_B1 * 256)         // 176128 (48 KB: [tap][i16][o row 16B])
#define OFF_BIAS  (OFF_W + 49152)               // 225280
#define OFF_IDXG0 (OFF_BIAS + 768)              // 226048 (230 ints gather idx)
#define OFF_IDXG1 (OFF_IDXG0 + 960)             // 227008
#define OFF_IDXS0 (OFF_IDXG1 + 960)             // 227968 (224 ints scatter idx)
#define OFF_IDXS1 (OFF_IDXS0 + 896)             // 228864
#define OFF_TM    (OFF_IDXS1 + 896)             // 229760
#define OFF_MBAR  (OFF_TM + 16)                 // 229776
#define OFF_WORK  (OFF_MBAR + 16)               // 229792
#define SMEM_BYTES (OFF_WORK + 16)              // 229808

// idesc: D=f32, A=B=tf32, N=64, M=128, K-major, cg1
#define IDESC 0x08100910u

// Device scratch
__device__ float g_mid[(size_t)NBATCH * NPTS * CH];
__device__ float g_wt2[NBLK * 3 * 3 * 16 * 256];   // [bl(6)][tap][i16][o*4+i%4], BN-folded tf32
__device__ float g_bias[NBLK * 3 * CH];
__device__ int   g_comp[NBATCH * NPTS];            // composed scatter idx for block 1
__device__ int   g_ctr[2];                         // work-stealing counters
__device__ int   g_is64;

__device__ __forceinline__ uint32_t smem_u32(const void* p) {
    uint32_t a;
    asm("{ .reg .u64 t; cvta.to.shared.u64 t, %1; cvt.u32.u64 %0, t; }" : "=r"(a) : "l"(p));
    return a;
}

// cp.async 16B with zero-fill when invalid (src-size 0)
__device__ __forceinline__ void cp16(uint32_t dst, const void* src, int valid) {
    int sz = valid ? 16 : 0;
    asm volatile("cp.async.cg.shared.global [%0], [%1], 16, %2;" :: "r"(dst), "l"(src), "r"(sz) : "memory");
}
#define CP_COMMIT() asm volatile("cp.async.commit_group;" ::: "memory")
#define CP_WAIT0()  asm volatile("cp.async.wait_group 0;" ::: "memory")

#if HAS_TC
// ---------------------------------------------------------------------------
__device__ __forceinline__ uint32_t elect_one() {
    uint32_t p;
    asm volatile("{\n\t.reg .pred p;\n\telect.sync _|p, 0xFFFFFFFF;\n\tselp.b32 %0, 1, 0, p;\n\t}" : "=r"(p));
    return p;
}
#define TCGEN05_ALLOC(sl, n)  asm volatile("tcgen05.alloc.cta_group::1.sync.aligned.shared::cta.b32 [%0], %1;" :: "r"(sl), "r"((uint32_t)(n)) : "memory")
#define TCGEN05_DEALLOC(t, n) asm volatile("tcgen05.dealloc.cta_group::1.sync.aligned.b32 %0, %1;" :: "r"(t), "r"((uint32_t)(n)))
#define TCGEN05_RELINQ()      asm volatile("tcgen05.relinquish_alloc_permit.cta_group::1.sync.aligned;")
#define TCGEN05_COMMIT(mb)    asm volatile("tcgen05.commit.cta_group::1.mbarrier::arrive::one.shared::cluster.b64 [%0];" :: "r"(mb) : "memory")
#define TCGEN05_WAIT_LD()     asm volatile("tcgen05.wait::ld.sync.aligned;" ::: "memory")
#define TCGEN05_FENCE_AFTER() asm volatile("tcgen05.fence::after_thread_sync;" ::: "memory")
#define TCGEN05_FENCE_BEFORE() asm volatile("tcgen05.fence::before_thread_sync;" ::: "memory")
#define FENCE_ASYNC()         asm volatile("fence.proxy.async.shared::cta;" ::: "memory")
#define MBAR_INIT(mb, n)      asm volatile("mbarrier.init.shared.b64 [%0], %1;" :: "r"(mb), "r"((uint32_t)(n)) : "memory")

#define MBAR_WAIT(mb, ph) do {                                                   \
    uint32_t _m = (mb), _p = (ph), _d;                                           \
    asm volatile("{\n\t.reg .pred p;\n\t"                                        \
        "mbarrier.try_wait.parity.acquire.cta.shared::cta.b64 p, [%1], %2;\n\t"  \
        "selp.b32 %0, 1, 0, p;\n\t}" : "=r"(_d) : "r"(_m), "r"(_p) : "memory");  \
    if (!_d) {                                                                   \
        asm volatile("{\n\t.reg .pred P1;\n\t"                                   \
        "WL_%=:\n\t"                                                             \
        "mbarrier.try_wait.parity.acquire.cta.shared::cta.b64 P1, [%0], %1, 0x989680;\n\t" \
        "@P1 bra.uni WD_%=;\n\t"                                                 \
        "bra.uni WL_%=;\n\t"                                                     \
        "WD_%=:\n\t}" :: "r"(_m), "r"(_p) : "memory");                           \
    }                                                                            \
} while (0)

#define LDTM_X32(r, addr) \
    asm volatile("tcgen05.ld.sync.aligned.32x32b.x32.b32 " \
        "{%0, %1, %2, %3, %4, %5, %6, %7, " \
        " %8, %9, %10, %11, %12, %13, %14, %15, " \
        " %16, %17, %18, %19, %20, %21, %22, %23, " \
        " %24, %25, %26, %27, %28, %29, %30, %31}, [%32];" \
        : "=r"((r)[0]),  "=r"((r)[1]),  "=r"((r)[2]),  "=r"((r)[3]), \
          "=r"((r)[4]),  "=r"((r)[5]),  "=r"((r)[6]),  "=r"((r)[7]), \
          "=r"((r)[8]),  "=r"((r)[9]),  "=r"((r)[10]), "=r"((r)[11]), \
          "=r"((r)[12]), "=r"((r)[13]), "=r"((r)[14]), "=r"((r)[15]), \
          "=r"((r)[16]), "=r"((r)[17]), "=r"((r)[18]), "=r"((r)[19]), \
          "=r"((r)[20]), "=r"((r)[21]), "=r"((r)[22]), "=r"((r)[23]), \
          "=r"((r)[24]), "=r"((r)[25]), "=r"((r)[26]), "=r"((r)[27]), \
          "=r"((r)[28]), "=r"((r)[29]), "=r"((r)[30]), "=r"((r)[31]) \
        : "r"(addr))

__device__ __forceinline__ void mma_tf32(uint32_t d, uint64_t ad, uint64_t bd, uint32_t en) {
    asm volatile("{\n\t.reg .pred p;\n\tsetp.ne.u32 p, %4, 0;\n\t"
        "tcgen05.mma.cta_group::1.kind::tf32 [%0], %1, %2, %3, {%5, %5, %5, %5}, p;\n\t}"
        :: "r"(d), "l"(ad), "l"(bd), "r"(IDESC), "r"(en), "r"(0u) : "memory");
}

__device__ __forceinline__ uint64_t make_desc(uint32_t addr, uint32_t lbo, uint32_t sbo) {
    uint64_t d = (uint64_t)((addr >> 4) & 0x3FFF);
    d |= (uint64_t)(lbo & 0x3FFF) << 16;
    d |= (uint64_t)(sbo & 0x3FFF) << 32;
    d |= (uint64_t)1 << 46;
    return d;
}

// One conv layer, per-M-tile commit: tile0 -> mbar0, tile1 -> mbar1.
__device__ __forceinline__ void issue_conv(uint32_t aAddr, int aLBO, uint32_t wAddr,
                                           uint32_t tmemD, uint32_t mbar) {
    uint64_t ab = make_desc(aAddr, aLBO, 8);
    uint64_t bb = make_desc(wAddr, 64, 8);
#pragma unroll
    for (int T = 0; T < 2; T++) {
        uint32_t en = 0;
#pragma unroll
        for (int tap = 0; tap < 3; tap++)
#pragma unroll
            for (int ks = 0; ks < 8; ks++) {
                mma_tf32(tmemD + T * 64,
                         ab + (uint64_t)(T * 128 + tap + 2 * ks * aLBO),
                         bb + (uint64_t)(tap * 1024 + 2 * ks * 64), en);
                en = 1;
            }
        TCGEN05_COMMIT(mbar + T * 8);
    }
}
#else  // !HAS_TC -----------------------------------------------------------
__device__ void conv_scalar(char* smem, int offIn, int rowsIn, int offOut, int rowsOut,
                            int live, int posBase, const float* sW,
                            const float* sBiasL, int tid) {
    for (int r = tid; r < live; r += NTHREADS) {
        float acc[CH];
#pragma unroll
        for (int o = 0; o < CH; o++) acc[o] = 0.f;
        bool zero = (posBase + r < 0) || (posBase + r >= NPTS);
        if (!zero) {
            for (int tap = 0; tap < 3; tap++)
                for (int ci = 0; ci < 16; ci++) {
                    const float* inp = (const float*)(smem + offIn + ((size_t)ci * rowsIn + r + tap) * 16);
                    float x0 = inp[0], x1 = inp[1], x2 = inp[2], x3 = inp[3];
                    const float* wp = sW + tap * 4096 + ci * 256;
                    for (int o = 0; o < CH; o++)
                        acc[o] += x0 * wp[o * 4] + x1 * wp[o * 4 + 1]
                                + x2 * wp[o * 4 + 2] + x3 * wp[o * 4 + 3];
                }
        }
        for (int ci = 0; ci < 16; ci++) {
            float4 v = make_float4(0.f, 0.f, 0.f, 0.f);
            if (!zero) {
                if (sBiasL) {
                    v.x = fmaxf(acc[ci * 4 + 0] + sBiasL[ci * 4 + 0], 0.f);
                    v.y = fmaxf(acc[ci * 4 + 1] + sBiasL[ci * 4 + 1], 0.f);
                    v.z = fmaxf(acc[ci * 4 + 2] + sBiasL[ci * 4 + 2], 0.f);
                    v.w = fmaxf(acc[ci * 4 + 3] + sBiasL[ci * 4 + 3], 0.f);
                } else {
                    v = make_float4(acc[ci * 4], acc[ci * 4 + 1], acc[ci * 4 + 2], acc[ci * 4 + 3]);
                }
            }
            *(float4*)(smem + offOut + ((size_t)ci * rowsOut + r) * 16) = v;
        }
    }
}
#endif // HAS_TC

// ---------------------------------------------------------------------------
// Prep kernels
// ---------------------------------------------------------------------------
__global__ void detect_idx_kernel(const unsigned int* __restrict__ w) {
    __shared__ int any;
    if (threadIdx.x == 0) { any = 0; g_ctr[0] = 0; g_ctr[1] = 0; }
    __syncthreads();
    int local = 0;
    for (int i = threadIdx.x; i < 2048; i += blockDim.x)
        if (w[2 * i + 1] != 0u) local = 1;
    if (local) atomicOr(&any, 1);
    __syncthreads();
    if (threadIdx.x == 0) g_is64 = any ? 0 : 1;
}

__global__ void repack_kernel(const float* __restrict__ w,
                              const float* __restrict__ gm,
                              const float* __restrict__ bt,
                              const float* __restrict__ mn,
                              const float* __restrict__ vr) {
    int idx = blockIdx.x * blockDim.x + threadIdx.x;
    if (idx >= NBLK * 3 * CH * CH) return;
    int i  = idx & 63;
    int o  = (idx >> 6) & 63;
    int bl = idx >> 12;
    float scale = gm[bl * CH + o] * rsqrtf(vr[bl * CH + o] + 1e-5f);
#pragma unroll
    for (int t = 0; t < 3; t++) {
        float val = w[(((size_t)bl * CH + o) * CH + i) * 3 + t] * scale;
        g_wt2[(size_t)bl * 12288 + ((t * 16 + (i >> 2)) * 256) + o * 4 + (i & 3)] =
            nvcuda::wmma::__float_to_tf32(val);
    }
    if (i == 0)
        g_bias[bl * CH + o] = bt[bl * CH + o] - mn[bl * CH + o] * scale;
}

// comp[b][p] = re2[b][ pa1[b][p] ]
__global__ void compose_kernel(const void* __restrict__ pa1, const void* __restrict__ re2) {
    int idx = blockIdx.x * blockDim.x + threadIdx.x;
    if (idx >= NBATCH * NPTS) return;
    int b = idx / NPTS;
    int is64 = g_is64;
    long long v1 = is64 ? ((const long long*)pa1)[idx] : (long long)((const int*)pa1)[idx];
    size_t j = (size_t)b * NPTS + (size_t)v1;
    int v2 = is64 ? (int)((const long long*)re2)[j] : ((const int*)re2)[j];
    g_comp[idx] = v2;
}

// ---------------------------------------------------------------------------
// Persistent fused block kernel, cross-work pipelined (TMEM ping-pong).
// ---------------------------------------------------------------------------
__global__ __launch_bounds__(NTHREADS, 1)
void block_kernel(const float* __restrict__ xin, float* __restrict__ xout,
                  const void* __restrict__ gIdx, int linearGather,
                  const void* __restrict__ scIdx, int scMode,
                  const float* __restrict__ wslab, const float* __restrict__ bias,
                  int* __restrict__ ctr) {
    extern __shared__ char smem[];
    const int tid  = threadIdx.x;
    const int warp = tid >> 5;
    const int lane = tid & 31;
    const int is64  = g_is64;
    const int sIs64 = scMode ? is64 : 0;

    const uint32_t sbase = smem_u32(smem);
    float* sBias = (float*)(smem + OFF_BIAS);
    float* sW    = (float*)(smem + OFF_W);
    int*   sWrk  = (int*)(smem + OFF_WORK);

    const int inOff[2]   = {OFF_IN0, OFF_IN1};
    const int idxGOff[2] = {OFF_IDXG0, OFF_IDXG1};
    const int idxSOff[2] = {OFF_IDXS0, OFF_IDXS1};

#if HAS_TC
    const uint32_t mbar = sbase + OFF_MBAR;
    if (tid == 0) { MBAR_INIT(mbar, 1); MBAR_INIT(mbar + 8, 1); }
    if (warp == 0) {
        TCGEN05_ALLOC(sbase + OFF_TM, 256);
        TCGEN05_RELINQ();
    }
#endif

    // steal first work + bias + layer-0 weights
    if (tid == 0) sWrk[0] = atomicAdd(ctr, 1);
    if (tid < 3 * CH) sBias[tid] = bias[tid];
#pragma unroll
    for (int k = 0; k < 6; k++)
        ((float4*)sW)[tid + k * NTHREADS] = ((const float4*)wslab)[tid + k * NTHREADS];
    __syncthreads();
    int work = sWrk[0];
    if (tid == 0) sWrk[0] = (work < NWORK) ? atomicAdd(ctr, 1) : NWORK;  // steal-ahead

    // ---- prologue: idx + gather for the first work ----
    if (work < NWORK) {
        int b0 = work / GRID_X, t0 = (work % GRID_X) * TILE;
        int* sG = (int*)(smem + OFF_IDXG0);
        int* sS = (int*)(smem + OFF_IDXS0);
        if (!linearGather) {
            for (int r = tid; r < R_IN; r += NTHREADS) {
                int p = t0 - 3 + r;
                int v = -1;
                if (p >= 0 && p < NPTS) {
                    size_t gp = (size_t)b0 * NPTS + p;
                    v = is64 ? (int)((const long long*)gIdx)[gp] : ((const int*)gIdx)[gp];
                }
                sG[r] = v;
            }
        }
        for (int r = tid; r < TILE; r += NTHREADS) {
            int p = t0 + r;
            int v = 0;
            if (p < NPTS) {
                size_t gp = (size_t)b0 * NPTS + p;
                v = sIs64 ? (int)((const long long*)scIdx)[gp] : ((const int*)scIdx)[gp];
            }
            sS[r] = v;
        }
        __syncthreads();
        const float* xb = xin + (size_t)b0 * NPTS * CH;
        for (int it = tid; it < R_IN * 16; it += NTHREADS) {
            int r = it >> 4, c = it & 15;
            if (!linearGather) {
                int src = sG[r];
                cp16(sbase + OFF_IN0 + (uint32_t)(c * R_IN + r) * 16,
                     (src >= 0) ? (const void*)(xb + (size_t)src * CH + c * 4) : (const void*)xin,
                     src >= 0);
            } else {
                int p = t0 - 3 + r;
                int valid = (p >= 0) && (p < NPTS);
                int pc = valid ? p : 0;
                cp16(sbase + OFF_IN0 + (uint32_t)(c * R_IN + r) * 16,
                     (const void*)(xb + (size_t)pc * CH + c * 4), valid);
            }
        }
    }
    CP_COMMIT();

#if HAS_TC
    uint32_t tmem;
    asm volatile("ld.shared.b32 %0, [%1];" : "=r"(tmem) : "r"(sbase + OFF_TM));

    CP_WAIT0();
    TCGEN05_FENCE_BEFORE();
    FENCE_ASYNC();
    __syncthreads();
    // issue conv1 of the first work (TMEM region 0)
    if (work < NWORK && warp == 0 && elect_one())
        issue_conv(sbase + OFF_IN0, R_IN, sbase + OFF_W, tmem, mbar);
    int wnext = sWrk[0];

    // Warp mapping: tile = w>>3, colhalf = (w>>2)&1, subpartition = w&3
    const int mtile = warp >> 3;
    const int colh  = (warp >> 2) & 1;
    const int myrow = mtile * 128 + (warp & 3) * 32 + lane;
    const uint32_t mymbar = mbar + mtile * 8;
    const uint32_t otmbar = mbar + (1 - mtile) * 8;

    int ph = 0, cur = 0, treg = 0;
    while (work < NWORK) {
        const int b     = work / GRID_X;
        const int tile0 = (work % GRID_X) * TILE;
        const int nxt   = cur ^ 1;
        char* INp = smem + inOff[cur];
        int* sG_n = (int*)(smem + idxGOff[nxt]);
        int* sS_c = (int*)(smem + idxSOff[cur]);
        int* sS_n = (int*)(smem + idxSOff[nxt]);
        const uint32_t dreg  = tmem + treg * 128;
        const uint32_t dregN = tmem + (treg ^ 1) * 128;
        const uint32_t dcol  = dreg + mtile * 64 + colh * 32;

        // ===== phase 1: conv1 in flight (pre-issued) =====
        if (wnext < NWORK) {   // next-work indices, under conv1
            int bn = wnext / GRID_X, tn = (wnext % GRID_X) * TILE;
            if (!linearGather) {
                for (int r = tid; r < R_IN; r += NTHREADS) {
                    int p = tn - 3 + r;
                    int v = -1;
                    if (p >= 0 && p < NPTS) {
                        size_t gp = (size_t)bn * NPTS + p;
                        v = is64 ? (int)((const long long*)gIdx)[gp] : ((const int*)gIdx)[gp];
                    }
                    sG_n[r] = v;
                }
            }
            for (int r = tid; r < TILE; r += NTHREADS) {
                int p = tn + r;
                int v = 0;
                if (p < NPTS) {
                    size_t gp = (size_t)bn * NPTS + p;
                    v = sIs64 ? (int)((const long long*)scIdx)[gp] : ((const int*)scIdx)[gp];
                }
                sS_n[r] = v;
            }
        }
        float4 wreg[6];
#pragma unroll
        for (int k = 0; k < 6; k++) wreg[k] = ((const float4*)(wslab + 12288))[tid + k * NTHREADS];

        MBAR_WAIT(mymbar, ph);
        TCGEN05_FENCE_AFTER();
        {
            uint32_t rg[32];
            LDTM_X32(rg, dcol);
            MBAR_WAIT(otmbar, ph);          // other tile's conv1 drain, under LDTM latency
            TCGEN05_WAIT_LD();
            int r = myrow, p = tile0 - 2 + r;
            if (r < R_B1) {
                bool zero = (p < 0) || (p >= NPTS);
#pragma unroll
                for (int j = 0; j < 8; j++) {
                    int c = colh * 8 + j;
                    float4 v = make_float4(0.f, 0.f, 0.f, 0.f);
                    if (!zero) {
                        float4 bb = *(const float4*)(sBias + c * 4);
                        v.x = fmaxf(__uint_as_float(rg[j * 4 + 0]) + bb.x, 0.f);
                        v.y = fmaxf(__uint_as_float(rg[j * 4 + 1]) + bb.y, 0.f);
                        v.z = fmaxf(__uint_as_float(rg[j * 4 + 2]) + bb.z, 0.f);
                        v.w = fmaxf(__uint_as_float(rg[j * 4 + 3]) + bb.w, 0.f);
                    }
                    *(float4*)(smem + OFF_B1 + ((size_t)c * R_B1 + r) * 16) = v;
                }
            }
        }
#pragma unroll
        for (int k = 0; k < 6; k++) ((float4*)sW)[tid + k * NTHREADS] = wreg[k];
        ph ^= 1;
        TCGEN05_FENCE_BEFORE();
        FENCE_ASYNC();
        __syncthreads();

        // ===== phase 2: conv2 =====
        if (warp == 0 && elect_one())
            issue_conv(sbase + OFF_B1, R_B1, sbase + OFF_W, dreg, mbar);
        if (tid == 0) sWrk[0] = (wnext < NWORK) ? atomicAdd(ctr, 1) : NWORK;

        if (wnext < NWORK) {   // next-work gather, under conv2
            int bn = wnext / GRID_X, tn = (wnext % GRID_X) * TILE;
            const float* xb = xin + (size_t)bn * NPTS * CH;
            for (int it = tid; it < R_IN * 16; it += NTHREADS) {
                int r = it >> 4, c = it & 15;
                if (!linearGather) {
                    int src = sG_n[r];
                    cp16(sbase + inOff[nxt] + (uint32_t)(c * R_IN + r) * 16,
                         (src >= 0) ? (const void*)(xb + (size_t)src * CH + c * 4) : (const void*)xin,
                         src >= 0);
                } else {
                    int p = tn - 3 + r;
                    int valid = (p >= 0) && (p < NPTS);
                    int pc = valid ? p : 0;
                    cp16(sbase + inOff[nxt] + (uint32_t)(c * R_IN + r) * 16,
                         (const void*)(xb + (size_t)pc * CH + c * 4), valid);
                }
            }
        }
        CP_COMMIT();
#pragma unroll
        for (int k = 0; k < 6; k++) wreg[k] = ((const float4*)(wslab + 24576))[tid + k * NTHREADS];

        MBAR_WAIT(mymbar, ph);
        TCGEN05_FENCE_AFTER();
        {
            uint32_t rg2[32];
            LDTM_X32(rg2, dcol);
            MBAR_WAIT(otmbar, ph);          // ALL conv2 MMAs done reading B1
            TCGEN05_WAIT_LD();
            int r = myrow, p = tile0 - 1 + r;
            if (r < R_B2) {
                bool zero = (p < 0) || (p >= NPTS);
#pragma unroll
                for (int j = 0; j < 8; j++) {
                    int c = colh * 8 + j;
                    float4 v = make_float4(0.f, 0.f, 0.f, 0.f);
                    if (!zero) {
                        float4 bb = *(const float4*)(sBias + 64 + c * 4);
                        v.x = fmaxf(__uint_as_float(rg2[j * 4 + 0]) + bb.x, 0.f);
                        v.y = fmaxf(__uint_as_float(rg2[j * 4 + 1]) + bb.y, 0.f);
                        v.z = fmaxf(__uint_as_float(rg2[j * 4 + 2]) + bb.z, 0.f);
                        v.w = fmaxf(__uint_as_float(rg2[j * 4 + 3]) + bb.w, 0.f);
                    }
                    *(float4*)(smem + OFF_B1 + ((size_t)c * R_B2 + r) * 16) = v;
                }
            }
        }
#pragma unroll
        for (int k = 0; k < 6; k++) ((float4*)sW)[tid + k * NTHREADS] = wreg[k];
        ph ^= 1;
        TCGEN05_FENCE_BEFORE();
        FENCE_ASYNC();
        __syncthreads();

        // ===== phase 3: conv3, then pre-issue next work's conv1 =====
        if (warp == 0 && elect_one())
            issue_conv(sbase + OFF_B1, R_B2, sbase + OFF_W, dreg, mbar);

#pragma unroll
        for (int k = 0; k < 6; k++) wreg[k] = ((const float4*)wslab)[tid + k * NTHREADS];
        CP_WAIT0();                          // next gather complete
        MBAR_WAIT(mymbar, ph);
        MBAR_WAIT(otmbar, ph);               // conv3 done: D ready, W slab + B1 free
        TCGEN05_FENCE_AFTER();
#pragma unroll
        for (int k = 0; k < 6; k++) ((float4*)sW)[tid + k * NTHREADS] = wreg[k];
        ph ^= 1;
        TCGEN05_FENCE_BEFORE();
        FENCE_ASYNC();
        __syncthreads();
        if (wnext < NWORK && warp == 0 && elect_one())
            issue_conv(sbase + inOff[nxt], R_IN, sbase + OFF_W, dregN, mbar);

        // epilogue 3: runs under next work's conv1 MMAs
        {
            uint32_t rg[32];
            LDTM_X32(rg, dcol);
            TCGEN05_WAIT_LD();
            int r = myrow;
            bool go = (r < TILE) && (tile0 + r < NPTS);
            if (go) {
                int dst = sS_c[r];
                float* outp = xout + ((size_t)b * NPTS + dst) * CH;
#pragma unroll
                for (int j = 0; j < 8; j++) {
                    int c = colh * 8 + j;
                    float4 res = *(const float4*)(INp + ((size_t)c * R_IN + (r + 3)) * 16);
                    float4 bb  = *(const float4*)(sBias + 128 + c * 4);
                    float4 y;
                    y.x = fmaxf(res.x + __uint_as_float(rg[j * 4 + 0]) + bb.x, 0.f);
                    y.y = fmaxf(res.y + __uint_as_float(rg[j * 4 + 1]) + bb.y, 0.f);
                    y.z = fmaxf(res.z + __uint_as_float(rg[j * 4 + 2]) + bb.z, 0.f);
                    y.w = fmaxf(res.w + __uint_as_float(rg[j * 4 + 3]) + bb.w, 0.f);
                    *(float4*)(outp + c * 4) = y;
                }
            }
        }
        TCGEN05_FENCE_BEFORE();
        __syncthreads();

        work = wnext;
        wnext = sWrk[0];
        cur ^= 1;
        treg ^= 1;
    }
    if (warp == 0) TCGEN05_DEALLOC(tmem, 256);

#else // ---- scalar fallback (compute_103 JIT image only): static striding ----
    CP_WAIT0();
    __syncthreads();
    for (int w2 = blockIdx.x; w2 < NWORK; w2 += gridDim.x) {
        const int b     = w2 / GRID_X;
        const int tile0 = (w2 % GRID_X) * TILE;
        int* sG = (int*)(smem + OFF_IDXG0);
        int* sS = (int*)(smem + OFF_IDXS0);
        __syncthreads();
        if (!linearGather) {
            for (int r = tid; r < R_IN; r += NTHREADS) {
                int p = tile0 - 3 + r;
                int v = -1;
                if (p >= 0 && p < NPTS) {
                    size_t gp = (size_t)b * NPTS + p;
                    v = is64 ? (int)((const long long*)gIdx)[gp] : ((const int*)gIdx)[gp];
                }
                sG[r] = v;
            }
        }
        for (int r = tid; r < TILE; r += NTHREADS) {
            int p = tile0 + r;
            int v = 0;
            if (p < NPTS) {
                size_t gp = (size_t)b * NPTS + p;
                v = sIs64 ? (int)((const long long*)scIdx)[gp] : ((const int*)scIdx)[gp];
            }
            sS[r] = v;
        }
        __syncthreads();
        const float* xb = xin + (size_t)b * NPTS * CH;
        for (int it = tid; it < R_IN * 16; it += NTHREADS) {
            int r = it >> 4, c = it & 15;
            float4 v = make_float4(0.f, 0.f, 0.f, 0.f);
            if (!linearGather) {
                int src = sG[r];
                if (src >= 0) v = *(const float4*)(xb + (size_t)src * CH + c * 4);
            } else {
                int p = tile0 - 3 + r;
                if (p >= 0 && p < NPTS) v = *(const float4*)(xb + (size_t)p * CH + c * 4);
            }
            *(float4*)(smem + OFF_IN0 + ((size_t)c * R_IN + r) * 16) = v;
        }
        __syncthreads();
        conv_scalar(smem, OFF_IN0, R_IN, OFF_B1, R_B1, R_B1, tile0 - 2, sW, sBias, tid);
        __syncthreads();
        for (int it = tid; it < 3072; it += NTHREADS)
            ((float4*)sW)[it] = ((const float4*)(wslab + 12288))[it];
        __syncthreads();
        conv_scalar(smem, OFF_B1, R_B1, OFF_IN1, R_B2, R_B2, tile0 - 1, sW, sBias + 64, tid);
        __syncthreads();
        for (int it = tid; it < 3072; it += NTHREADS)
            ((float4*)sW)[it] = ((const float4*)(wslab + 24576))[it];
        __syncthreads();
        conv_scalar(smem, OFF_IN1, R_B2, OFF_B1, R_B1, TILE, tile0, sW, nullptr, tid);
        __syncthreads();
        for (int it = tid; it < TILE * 16; it += NTHREADS) {
            int r = it >> 4, c = it & 15;
            if (tile0 + r >= NPTS) continue;
            int dst = sS[r];
            float4 h   = *(const float4*)(smem + OFF_B1 + ((size_t)c * R_B1 + r) * 16);
            float4 res = *(const float4*)(smem + OFF_IN0 + ((size_t)c * R_IN + (r + 3)) * 16);
            float4 bb  = *(const float4*)(sBias + 128 + c * 4);
            float4 y;
            y.x = fmaxf(res.x + h.x + bb.x, 0.f);
            y.y = fmaxf(res.y + h.y + bb.y, 0.f);
            y.z = fmaxf(res.z + h.z + bb.z, 0.f);
            y.w = fmaxf(res.w + h.w + bb.w, 0.f);
            *(float4*)(xout + ((size_t)b * NPTS + dst) * CH + c * 4) = y;
        }
        __syncthreads();
        for (int it = tid; it < 3072; it += NTHREADS)
            ((float4*)sW)[it] = ((const float4*)wslab)[it];
        __syncthreads();
    }
#endif
}

// ---------------------------------------------------------------------------
// Launch
// ---------------------------------------------------------------------------
extern "C" void kernel_launch(void* const* d_in, const int* in_sizes, int n_in,
                              void* d_out, int out_size) {
    const float* x      = (const float*)d_in[0];
    const void*  pa1    = d_in[1];
    const void*  pa2    = d_in[3];
    const void*  re2    = d_in[4];
    const float* conv_w = (const float*)d_in[5];
    const float* gma    = (const float*)d_in[6];
    const float* bta    = (const float*)d_in[7];
    const float* mean   = (const float*)d_in[8];
    const float* var    = (const float*)d_in[9];

    float* mid;  cudaGetSymbolAddress((void**)&mid,  g_mid);
    float* wt2;  cudaGetSymbolAddress((void**)&wt2,  g_wt2);
    float* bias; cudaGetSymbolAddress((void**)&bias, g_bias);
    int*   comp; cudaGetSymbolAddress((void**)&comp, g_comp);
    int*   ctr;  cudaGetSymbolAddress((void**)&ctr,  g_ctr);

    int nsm = 148;
    cudaDeviceGetAttribute(&nsm, cudaDevAttrMultiProcessorCount, 0);

    cudaFuncSetAttribute(block_kernel, cudaFuncAttributeMaxDynamicSharedMemorySize, SMEM_BYTES);

    detect_idx_kernel<<<1, 256>>>((const unsigned int*)pa1);
    repack_kernel<<<(NBLK * 3 * CH * CH + 255) / 256, 256>>>(conv_w, gma, bta, mean, var);
    compose_kernel<<<(NBATCH * NPTS + 255) / 256, 256>>>(pa1, re2);

    // block 1: x --(gather pa1)--> conv --(scatter comp)--> mid (block2-gather order)
    block_kernel<<<nsm, NTHREADS, SMEM_BYTES>>>(x, mid, pa1, 0, comp, 0, wt2, bias, ctr);
    // block 2: mid --(linear gather)--> conv --(scatter pa2)--> out
    block_kernel<<<nsm, NTHREADS, SMEM_BYTES>>>(mid, (float*)d_out, nullptr, 1,
                                                pa2, 1, wt2 + 3 * 12288, bias + 3 * CH,
                                                ctr + 1);
}

// round 11
// speedup vs baseline: 1.4272x; 1.4272x over previous
#include <cuda_runtime.h>
#include <cuda_fp16.h>
#include <cstdint>
#include <cstddef>

// tcgen05 is arch-SPECIFIC: only on the sm_103a pass; plain compute_103 gets a fallback.
#if defined(__CUDA_ARCH__) && (defined(__CUDA_ARCH_FEAT_SM103_ALL) || defined(__CUDA_ARCH_FEAT_SM100_ALL) || defined(__CUDA_ARCH_FEAT_SM101_ALL))
#define HAS_TC 1
#else
#define HAS_TC 0
#endif

// Problem constants
#define NBATCH   2
#define CH       64
#define NPTS     262144
#define NBLK     2

// Tiling
#define TILE     224
#define R_IN     230
#define R_B1     228
#define R_B2     226
#define NTHREADS 512
#define GRID_X   ((NPTS + TILE - 1) / TILE)   // 1171
#define NWORK    (GRID_X * NBATCH)            // 2342

// SMEM layout (fp16 activations). Canonical K-major chunks: 16B unit = 8 fp16
// channels; addr = chunk*ROWS*16 + row*16. 8 chunks cover CH=64.
#define OFF_IN0   0
#define OFF_IN1   29440                          // 230*128
#define OFF_B1    58880
#define OFF_W     88064                          // 3 resident slabs x 24576B
#define OFF_BIAS  161792                         // 3 x 64 floats
#define OFF_IDXG0 162560                         // 230 ints
#define OFF_IDXG1 163520
#define OFF_IDXS0 164480                         // 224 ints
#define OFF_IDXS1 165376
#define OFF_TM    166272
#define OFF_MBAR  166288
#define OFF_WORK  166304
#define SMEM_BYTES 166320

// idesc kind::f16: D=f32(1<<4), A=B=FP16(0), N=64 (8<<17), M=128 (8<<24)
#define IDESC_F16 0x08100010u

// Device scratch
__device__ __half g_mid[(size_t)NBATCH * NPTS * CH];   // inter-block activations, fp16 (64MB)
__device__ __half g_wh[NBLK * 3 * 3 * 8 * 64 * 8];     // [bl(6)][tap][kc8][o64][i%8], BN-folded fp16
__device__ float  g_bias[NBLK * 3 * CH];
__device__ int    g_comp[NBATCH * NPTS];               // composed scatter idx for block 1
__device__ int    g_ctr[2];                            // work-stealing counters
__device__ int    g_is64;

__device__ __forceinline__ uint32_t smem_u32(const void* p) {
    uint32_t a;
    asm("{ .reg .u64 t; cvta.to.shared.u64 t, %1; cvt.u32.u64 %0, t; }" : "=r"(a) : "l"(p));
    return a;
}

// cp.async 16B with zero-fill when invalid (src-size 0)
__device__ __forceinline__ void cp16(uint32_t dst, const void* src, int valid) {
    int sz = valid ? 16 : 0;
    asm volatile("cp.async.cg.shared.global [%0], [%1], 16, %2;" :: "r"(dst), "l"(src), "r"(sz) : "memory");
}
#define CP_COMMIT() asm volatile("cp.async.commit_group;" ::: "memory")
#define CP_WAIT0()  asm volatile("cp.async.wait_group 0;" ::: "memory")

__device__ __forceinline__ uint32_t packh2(float a, float b) {
    __half2 h = __floats2half2_rn(a, b);
    return *(uint32_t*)&h;
}

#if HAS_TC
// ---------------------------------------------------------------------------
__device__ __forceinline__ uint32_t elect_one() {
    uint32_t p;
    asm volatile("{\n\t.reg .pred p;\n\telect.sync _|p, 0xFFFFFFFF;\n\tselp.b32 %0, 1, 0, p;\n\t}" : "=r"(p));
    return p;
}
#define TCGEN05_ALLOC(sl, n)  asm volatile("tcgen05.alloc.cta_group::1.sync.aligned.shared::cta.b32 [%0], %1;" :: "r"(sl), "r"((uint32_t)(n)) : "memory")
#define TCGEN05_DEALLOC(t, n) asm volatile("tcgen05.dealloc.cta_group::1.sync.aligned.b32 %0, %1;" :: "r"(t), "r"((uint32_t)(n)))
#define TCGEN05_RELINQ()      asm volatile("tcgen05.relinquish_alloc_permit.cta_group::1.sync.aligned;")
#define TCGEN05_COMMIT(mb)    asm volatile("tcgen05.commit.cta_group::1.mbarrier::arrive::one.shared::cluster.b64 [%0];" :: "r"(mb) : "memory")
#define TCGEN05_WAIT_LD()     asm volatile("tcgen05.wait::ld.sync.aligned;" ::: "memory")
#define TCGEN05_FENCE_AFTER() asm volatile("tcgen05.fence::after_thread_sync;" ::: "memory")
#define TCGEN05_FENCE_BEFORE() asm volatile("tcgen05.fence::before_thread_sync;" ::: "memory")
#define FENCE_ASYNC()         asm volatile("fence.proxy.async.shared::cta;" ::: "memory")
#define MBAR_INIT(mb, n)      asm volatile("mbarrier.init.shared.b64 [%0], %1;" :: "r"(mb), "r"((uint32_t)(n)) : "memory")

#define MBAR_WAIT(mb, ph) do {                                                   \
    uint32_t _m = (mb), _p = (ph), _d;                                           \
    asm volatile("{\n\t.reg .pred p;\n\t"                                        \
        "mbarrier.try_wait.parity.acquire.cta.shared::cta.b64 p, [%1], %2;\n\t"  \
        "selp.b32 %0, 1, 0, p;\n\t}" : "=r"(_d) : "r"(_m), "r"(_p) : "memory");  \
    if (!_d) {                                                                   \
        asm volatile("{\n\t.reg .pred P1;\n\t"                                   \
        "WL_%=:\n\t"                                                             \
        "mbarrier.try_wait.parity.acquire.cta.shared::cta.b64 P1, [%0], %1, 0x989680;\n\t" \
        "@P1 bra.uni WD_%=;\n\t"                                                 \
        "bra.uni WL_%=;\n\t"                                                     \
        "WD_%=:\n\t}" :: "r"(_m), "r"(_p) : "memory");                           \
    }                                                                            \
} while (0)

#define LDTM_X32(r, addr) \
    asm volatile("tcgen05.ld.sync.aligned.32x32b.x32.b32 " \
        "{%0, %1, %2, %3, %4, %5, %6, %7, " \
        " %8, %9, %10, %11, %12, %13, %14, %15, " \
        " %16, %17, %18, %19, %20, %21, %22, %23, " \
        " %24, %25, %26, %27, %28, %29, %30, %31}, [%32];" \
        : "=r"((r)[0]),  "=r"((r)[1]),  "=r"((r)[2]),  "=r"((r)[3]), \
          "=r"((r)[4]),  "=r"((r)[5]),  "=r"((r)[6]),  "=r"((r)[7]), \
          "=r"((r)[8]),  "=r"((r)[9]),  "=r"((r)[10]), "=r"((r)[11]), \
          "=r"((r)[12]), "=r"((r)[13]), "=r"((r)[14]), "=r"((r)[15]), \
          "=r"((r)[16]), "=r"((r)[17]), "=r"((r)[18]), "=r"((r)[19]), \
          "=r"((r)[20]), "=r"((r)[21]), "=r"((r)[22]), "=r"((r)[23]), \
          "=r"((r)[24]), "=r"((r)[25]), "=r"((r)[26]), "=r"((r)[27]), \
          "=r"((r)[28]), "=r"((r)[29]), "=r"((r)[30]), "=r"((r)[31]) \
        : "r"(addr))

__device__ __forceinline__ void mma_f16(uint32_t d, uint64_t ad, uint64_t bd, uint32_t en) {
    asm volatile("{\n\t.reg .pred p;\n\tsetp.ne.u32 p, %4, 0;\n\t"
        "tcgen05.mma.cta_group::1.kind::f16 [%0], %1, %2, %3, {%5, %5, %5, %5}, p;\n\t}"
        :: "r"(d), "l"(ad), "l"(bd), "r"(IDESC_F16), "r"(en), "r"(0u) : "memory");
}

__device__ __forceinline__ uint64_t make_desc(uint32_t addr, uint32_t lbo, uint32_t sbo) {
    uint64_t d = (uint64_t)((addr >> 4) & 0x3FFF);
    d |= (uint64_t)(lbo & 0x3FFF) << 16;
    d |= (uint64_t)(sbo & 0x3FFF) << 32;
    d |= (uint64_t)1 << 46;
    return d;
}

// One conv layer (fp16, K=64 in 4 k-steps of 16), per-M-tile commit.
__device__ __forceinline__ void issue_conv(uint32_t aAddr, int aLBO, uint32_t wAddr,
                                           uint32_t tmemD, uint32_t mbar) {
    uint64_t ab = make_desc(aAddr, aLBO, 8);
    uint64_t bb = make_desc(wAddr, 64, 8);
#pragma unroll
    for (int T = 0; T < 2; T++) {
        uint32_t en = 0;
#pragma unroll
        for (int tap = 0; tap < 3; tap++)
#pragma unroll
            for (int ks = 0; ks < 4; ks++) {
                mma_f16(tmemD + T * 64,
                        ab + (uint64_t)(T * 128 + tap + 2 * ks * aLBO),
                        bb + (uint64_t)(tap * 512 + 2 * ks * 64), en);
                en = 1;
            }
        TCGEN05_COMMIT(mbar + T * 8);
    }
}
#endif // HAS_TC

// ---------------------------------------------------------------------------
// Gather one tile into fp16 canonical smem. Block 1: LDG fp32 + convert + STS.
// Block 2 (linearGather): cp.async 16B from fp16 mid.
// ---------------------------------------------------------------------------
__device__ __forceinline__ void gather_tile(char* smem, uint32_t sbase, int dstOff,
                                            const float* xin32, const __half* xin16,
                                            int linearGather, int bn, int tn,
                                            const int* sG, int tid) {
    if (linearGather) {
        const __half* xb = xin16 + (size_t)bn * NPTS * CH;
        for (int it = tid; it < R_IN * 8; it += NTHREADS) {
            int r = it >> 3, c = it & 7;
            int p = tn - 3 + r;
            int valid = (p >= 0) && (p < NPTS);
            int pc = valid ? p : 0;
            cp16(sbase + dstOff + (uint32_t)(c * R_IN + r) * 16,
                 xb + (size_t)pc * CH + c * 8, valid);
        }
    } else {
        const float* xb = xin32 + (size_t)bn * NPTS * CH;
        for (int it = tid; it < R_IN * 8; it += NTHREADS) {
            int r = it >> 3, c = it & 7;
            int src = sG[r];
            uint4 u = make_uint4(0u, 0u, 0u, 0u);
            if (src >= 0) {
                const float* sp = xb + (size_t)src * CH + c * 8;
                float4 a = *(const float4*)sp;
                float4 b2 = *(const float4*)(sp + 4);
                u.x = packh2(a.x, a.y);  u.y = packh2(a.z, a.w);
                u.z = packh2(b2.x, b2.y); u.w = packh2(b2.z, b2.w);
            }
            *(uint4*)(smem + dstOff + (size_t)(c * R_IN + r) * 16) = u;
        }
    }
}

// ---------------------------------------------------------------------------
// Prep kernels
// ---------------------------------------------------------------------------
__global__ void detect_idx_kernel(const unsigned int* __restrict__ w) {
    __shared__ int any;
    if (threadIdx.x == 0) { any = 0; g_ctr[0] = 0; g_ctr[1] = 0; }
    __syncthreads();
    int local = 0;
    for (int i = threadIdx.x; i < 2048; i += blockDim.x)
        if (w[2 * i + 1] != 0u) local = 1;
    if (local) atomicOr(&any, 1);
    __syncthreads();
    if (threadIdx.x == 0) g_is64 = any ? 0 : 1;
}

// Fold BN into W; pack fp16 canonical B layout [bl][tap][kc][o][i%8].
__global__ void repack_kernel(const float* __restrict__ w,
                              const float* __restrict__ gm,
                              const float* __restrict__ bt,
                              const float* __restrict__ mn,
                              const float* __restrict__ vr) {
    int idx = blockIdx.x * blockDim.x + threadIdx.x;
    if (idx >= NBLK * 3 * CH * CH) return;
    int i  = idx & 63;
    int o  = (idx >> 6) & 63;
    int bl = idx >> 12;
    float scale = gm[bl * CH + o] * rsqrtf(vr[bl * CH + o] + 1e-5f);
#pragma unroll
    for (int t = 0; t < 3; t++) {
        float val = w[(((size_t)bl * CH + o) * CH + i) * 3 + t] * scale;
        g_wh[(size_t)bl * 12288 + t * 4096 + (i >> 3) * 512 + o * 8 + (i & 7)] = __float2half(val);
    }
    if (i == 0)
        g_bias[bl * CH + o] = bt[bl * CH + o] - mn[bl * CH + o] * scale;
}

// comp[b][p] = re2[b][ pa1[b][p] ]
__global__ void compose_kernel(const void* __restrict__ pa1, const void* __restrict__ re2) {
    int idx = blockIdx.x * blockDim.x + threadIdx.x;
    if (idx >= NBATCH * NPTS) return;
    int b = idx / NPTS;
    int is64 = g_is64;
    long long v1 = is64 ? ((const long long*)pa1)[idx] : (long long)((const int*)pa1)[idx];
    size_t j = (size_t)b * NPTS + (size_t)v1;
    int v2 = is64 ? (int)((const long long*)re2)[j] : ((const int*)re2)[j];
    g_comp[idx] = v2;
}

// ---------------------------------------------------------------------------
// Persistent fused block kernel (fp16 tcgen05), work stealing, resident weights.
// ---------------------------------------------------------------------------
__global__ __launch_bounds__(NTHREADS, 1)
void block_kernel(const float* __restrict__ xin32, const __half* __restrict__ xin16,
                  float* __restrict__ xout32, __half* __restrict__ xout16, int outHalf,
                  const void* __restrict__ gIdx, int linearGather,
                  const void* __restrict__ scIdx, int scMode,
                  const __half* __restrict__ wslabH, const float* __restrict__ bias,
                  int* __restrict__ ctr) {
    extern __shared__ char smem[];
    const int tid  = threadIdx.x;
    const int warp = tid >> 5;
    const int lane = tid & 31;
    const int is64  = g_is64;
    const int sIs64 = scMode ? is64 : 0;

    const uint32_t sbase = smem_u32(smem);
    float* sBias = (float*)(smem + OFF_BIAS);
    int*   sWrk  = (int*)(smem + OFF_WORK);

    const int inOff[2]   = {OFF_IN0, OFF_IN1};
    const int idxGOff[2] = {OFF_IDXG0, OFF_IDXG1};
    const int idxSOff[2] = {OFF_IDXS0, OFF_IDXS1};

#if HAS_TC
    const uint32_t mbar = sbase + OFF_MBAR;
    if (tid == 0) { MBAR_INIT(mbar, 1); MBAR_INIT(mbar + 8, 1); }
    if (warp == 0) {
        TCGEN05_ALLOC(sbase + OFF_TM, 256);
        TCGEN05_RELINQ();
    }
#endif

    // steal first work + bias + ALL 3 weight slabs (resident)
    if (tid == 0) sWrk[0] = atomicAdd(ctr, 1);
    if (tid < 3 * CH) sBias[tid] = bias[tid];
#pragma unroll
    for (int k = 0; k < 9; k++)
        ((uint4*)(smem + OFF_W))[tid + k * NTHREADS] = ((const uint4*)wslabH)[tid + k * NTHREADS];
    __syncthreads();
    int work = sWrk[0];
    if (tid == 0) sWrk[0] = (work < NWORK) ? atomicAdd(ctr, 1) : NWORK;  // steal-ahead

    // ---- prologue: idx + gather for first work ----
    if (work < NWORK) {
        int b0 = work / GRID_X, t0 = (work % GRID_X) * TILE;
        int* sG = (int*)(smem + OFF_IDXG0);
        int* sS = (int*)(smem + OFF_IDXS0);
        if (!linearGather) {
            for (int r = tid; r < R_IN; r += NTHREADS) {
                int p = t0 - 3 + r;
                int v = -1;
                if (p >= 0 && p < NPTS) {
                    size_t gp = (size_t)b0 * NPTS + p;
                    v = is64 ? (int)((const long long*)gIdx)[gp] : ((const int*)gIdx)[gp];
                }
                sG[r] = v;
            }
        }
        for (int r = tid; r < TILE; r += NTHREADS) {
            int p = t0 + r;
            int v = 0;
            if (p < NPTS) {
                size_t gp = (size_t)b0 * NPTS + p;
                v = sIs64 ? (int)((const long long*)scIdx)[gp] : ((const int*)scIdx)[gp];
            }
            sS[r] = v;
        }
        __syncthreads();
        gather_tile(smem, sbase, OFF_IN0, xin32, xin16, linearGather, b0, t0, sG, tid);
    }
    CP_COMMIT();

#if HAS_TC
    uint32_t tmem;
    asm volatile("ld.shared.b32 %0, [%1];" : "=r"(tmem) : "r"(sbase + OFF_TM));

    CP_WAIT0();
    TCGEN05_FENCE_BEFORE();
    FENCE_ASYNC();
    __syncthreads();
    if (work < NWORK && warp == 0 && elect_one())
        issue_conv(sbase + OFF_IN0, R_IN, sbase + OFF_W, tmem, mbar);
    int wnext = sWrk[0];

    // Warp mapping: tile = w>>3, colhalf = (w>>2)&1, subpartition = w&3
    const int mtile = warp >> 3;
    const int colh  = (warp >> 2) & 1;
    const int myrow = mtile * 128 + (warp & 3) * 32 + lane;
    const uint32_t mymbar = mbar + mtile * 8;
    const uint32_t otmbar = mbar + (1 - mtile) * 8;

    int ph = 0, cur = 0, treg = 0;
    while (work < NWORK) {
        const int b     = work / GRID_X;
        const int tile0 = (work % GRID_X) * TILE;
        const int nxt   = cur ^ 1;
        char* INp = smem + inOff[cur];
        int* sG_n = (int*)(smem + idxGOff[nxt]);
        int* sS_c = (int*)(smem + idxSOff[cur]);
        int* sS_n = (int*)(smem + idxSOff[nxt]);
        const uint32_t dreg  = tmem + treg * 128;
        const uint32_t dregN = tmem + (treg ^ 1) * 128;
        const uint32_t dcol  = dreg + mtile * 64 + colh * 32;

        // ===== phase 1: conv1 in flight (pre-issued) =====
        if (wnext < NWORK) {   // next-work indices under conv1
            int bn = wnext / GRID_X, tn = (wnext % GRID_X) * TILE;
            if (!linearGather) {
                for (int r = tid; r < R_IN; r += NTHREADS) {
                    int p = tn - 3 + r;
                    int v = -1;
                    if (p >= 0 && p < NPTS) {
                        size_t gp = (size_t)bn * NPTS + p;
                        v = is64 ? (int)((const long long*)gIdx)[gp] : ((const int*)gIdx)[gp];
                    }
                    sG_n[r] = v;
                }
            }
            for (int r = tid; r < TILE; r += NTHREADS) {
                int p = tn + r;
                int v = 0;
                if (p < NPTS) {
                    size_t gp = (size_t)bn * NPTS + p;
                    v = sIs64 ? (int)((const long long*)scIdx)[gp] : ((const int*)scIdx)[gp];
                }
                sS_n[r] = v;
            }
        }

        MBAR_WAIT(mymbar, ph);
        TCGEN05_FENCE_AFTER();
        {
            uint32_t rg[32];
            LDTM_X32(rg, dcol);
            TCGEN05_WAIT_LD();
            int r = myrow, p = tile0 - 2 + r;
            if (r < R_B1) {
                bool zero = (p < 0) || (p >= NPTS);
                const float* bb = sBias + colh * 32;
#pragma unroll
                for (int k = 0; k < 4; k++) {
                    uint4 u = make_uint4(0u, 0u, 0u, 0u);
                    if (!zero) {
#pragma unroll
                        for (int t = 0; t < 4; t++) {
                            float a = fmaxf(__uint_as_float(rg[8 * k + 2 * t]) + bb[8 * k + 2 * t], 0.f);
                            float c2 = fmaxf(__uint_as_float(rg[8 * k + 2 * t + 1]) + bb[8 * k + 2 * t + 1], 0.f);
                            ((uint32_t*)&u)[t] = packh2(a, c2);
                        }
                    }
                    *(uint4*)(smem + OFF_B1 + ((size_t)(colh * 4 + k) * R_B1 + r) * 16) = u;
                }
            }
        }
        ph ^= 1;
        TCGEN05_FENCE_BEFORE();
        FENCE_ASYNC();
        __syncthreads();

        // ===== phase 2: conv2 (epilogue rewrites B1 in R_B2 layout) =====
        if (warp == 0 && elect_one())
            issue_conv(sbase + OFF_B1, R_B1, sbase + OFF_W + 24576, dreg, mbar);
        if (tid == 0) sWrk[0] = (wnext < NWORK) ? atomicAdd(ctr, 1) : NWORK;

        if (wnext < NWORK) {   // next-work gather under conv2
            int bn = wnext / GRID_X, tn = (wnext % GRID_X) * TILE;
            gather_tile(smem, sbase, inOff[nxt], xin32, xin16, linearGather, bn, tn, sG_n, tid);
        }
        CP_COMMIT();

        MBAR_WAIT(mymbar, ph);
        TCGEN05_FENCE_AFTER();
        {
            uint32_t rg2[32];
            LDTM_X32(rg2, dcol);
            MBAR_WAIT(otmbar, ph);   // ALL conv2 MMAs done reading B1 (hidden under LDTM)
            TCGEN05_WAIT_LD();
            int r = myrow, p = tile0 - 1 + r;
            if (r < R_B2) {
                bool zero = (p < 0) || (p >= NPTS);
                const float* bb = sBias + 64 + colh * 32;
#pragma unroll
                for (int k = 0; k < 4; k++) {
                    uint4 u = make_uint4(0u, 0u, 0u, 0u);
                    if (!zero) {
#pragma unroll
                        for (int t = 0; t < 4; t++) {
                            float a = fmaxf(__uint_as_float(rg2[8 * k + 2 * t]) + bb[8 * k + 2 * t], 0.f);
                            float c2 = fmaxf(__uint_as_float(rg2[8 * k + 2 * t + 1]) + bb[8 * k + 2 * t + 1], 0.f);
                            ((uint32_t*)&u)[t] = packh2(a, c2);
                        }
                    }
                    *(uint4*)(smem + OFF_B1 + ((size_t)(colh * 4 + k) * R_B2 + r) * 16) = u;
                }
            }
        }
        ph ^= 1;
        TCGEN05_FENCE_BEFORE();
        FENCE_ASYNC();
        __syncthreads();

        // ===== phase 3: conv3, pre-issue next conv1, epilogue+scatter =====
        if (warp == 0 && elect_one())
            issue_conv(sbase + OFF_B1, R_B2, sbase + OFF_W + 49152, dreg, mbar);

        CP_WAIT0();                      // next gather landed
        MBAR_WAIT(mymbar, ph);           // own conv3 tile done (commit covers all prior MMAs)
        TCGEN05_FENCE_AFTER();
        ph ^= 1;
        TCGEN05_FENCE_BEFORE();
        FENCE_ASYNC();
        __syncthreads();                 // both tiles' conv3 done; IN[nxt] visible
        if (wnext < NWORK && warp == 0 && elect_one())
            issue_conv(sbase + inOff[nxt], R_IN, sbase + OFF_W, dregN, mbar);

        {   // epilogue 3 under next work's conv1
            uint32_t rg[32];
            LDTM_X32(rg, dcol);
            TCGEN05_WAIT_LD();
            int r = myrow;
            bool go = (r < TILE) && (tile0 + r < NPTS);
            if (go) {
                int dst = sS_c[r];
                const float* bb = sBias + 128 + colh * 32;
#pragma unroll
                for (int k = 0; k < 4; k++) {
                    uint4 rv = *(const uint4*)(INp + ((size_t)(colh * 4 + k) * R_IN + (r + 3)) * 16);
                    float y[8];
#pragma unroll
                    for (int t = 0; t < 4; t++) {
                        __half2 hh = *(__half2*)(((uint32_t*)&rv) + t);
                        float2 rf = __half22float2(hh);
                        y[2 * t]     = fmaxf(rf.x + __uint_as_float(rg[8 * k + 2 * t])     + bb[8 * k + 2 * t], 0.f);
                        y[2 * t + 1] = fmaxf(rf.y + __uint_as_float(rg[8 * k + 2 * t + 1]) + bb[8 * k + 2 * t + 1], 0.f);
                    }
                    if (outHalf) {
                        uint4 u;
                        u.x = packh2(y[0], y[1]); u.y = packh2(y[2], y[3]);
                        u.z = packh2(y[4], y[5]); u.w = packh2(y[6], y[7]);
                        *(uint4*)(xout16 + ((size_t)b * NPTS + dst) * CH + (colh * 4 + k) * 8) = u;
                    } else {
                        float* op = xout32 + ((size_t)b * NPTS + dst) * CH + colh * 32 + 8 * k;
                        *(float4*)op       = make_float4(y[0], y[1], y[2], y[3]);
                        *(float4*)(op + 4) = make_float4(y[4], y[5], y[6], y[7]);
                    }
                }
            }
        }
        TCGEN05_FENCE_BEFORE();
        __syncthreads();

        work = wnext;
        wnext = sWrk[0];
        cur ^= 1;
        treg ^= 1;
    }
    if (warp == 0) TCGEN05_DEALLOC(tmem, 256);

#else // ---- scalar fp16 fallback (compute_103 JIT image only) ----
    CP_WAIT0();
    __syncthreads();
    const __half* sWh = (const __half*)(smem + OFF_W);
    for (int w2 = blockIdx.x; w2 < NWORK; w2 += gridDim.x) {
        const int b     = w2 / GRID_X;
        const int tile0 = (w2 % GRID_X) * TILE;
        int* sG = (int*)(smem + OFF_IDXG0);
        int* sS = (int*)(smem + OFF_IDXS0);
        __syncthreads();
        if (!linearGather) {
            for (int r = tid; r < R_IN; r += NTHREADS) {
                int p = tile0 - 3 + r;
                int v = -1;
                if (p >= 0 && p < NPTS) {
                    size_t gp = (size_t)b * NPTS + p;
                    v = is64 ? (int)((const long long*)gIdx)[gp] : ((const int*)gIdx)[gp];
                }
                sG[r] = v;
            }
        }
        for (int r = tid; r < TILE; r += NTHREADS) {
            int p = tile0 + r;
            int v = 0;
            if (p < NPTS) {
                size_t gp = (size_t)b * NPTS + p;
                v = sIs64 ? (int)((const long long*)scIdx)[gp] : ((const int*)scIdx)[gp];
            }
            sS[r] = v;
        }
        __syncthreads();
        // gather (sync) into IN0
        for (int it = tid; it < R_IN * 8; it += NTHREADS) {
            int r = it >> 3, c = it & 7;
            uint4 u = make_uint4(0u, 0u, 0u, 0u);
            if (linearGather) {
                int p = tile0 - 3 + r;
                if (p >= 0 && p < NPTS)
                    u = *(const uint4*)(xin16 + ((size_t)b * NPTS + p) * CH + c * 8);
            } else {
                int src = sG[r];
                if (src >= 0) {
                    const float* sp = xin32 + ((size_t)b * NPTS + src) * CH + c * 8;
                    float4 a = *(const float4*)sp, b2 = *(const float4*)(sp + 4);
                    u.x = packh2(a.x, a.y);  u.y = packh2(a.z, a.w);
                    u.z = packh2(b2.x, b2.y); u.w = packh2(b2.z, b2.w);
                }
            }
            *(uint4*)(smem + OFF_IN0 + (size_t)(c * R_IN + r) * 16) = u;
        }
        __syncthreads();
        // three scalar convs: IN0->B1, B1->IN1, IN1->B1 (raw)
        for (int layer = 0; layer < 3; layer++) {
            int offI = (layer == 0) ? OFF_IN0 : (layer == 1) ? OFF_B1 : OFF_IN1;
            int rI   = (layer == 0) ? R_IN : (layer == 1) ? R_B1 : R_B2;
            int offO = (layer == 1) ? OFF_IN1 : OFF_B1;
            int rO   = (layer == 0) ? R_B1 : (layer == 1) ? R_B2 : R_B1;
            int live = (layer == 0) ? R_B1 : (layer == 1) ? R_B2 : TILE;
            int pb   = tile0 - 2 + layer;
            const __half* wl = sWh + layer * 12288;
            for (int r = tid; r < live; r += NTHREADS) {
                float acc[CH];
#pragma unroll
                for (int o = 0; o < CH; o++) acc[o] = 0.f;
                bool zero = (pb + r < 0) || (pb + r >= NPTS);
                if (!zero) {
                    for (int tap = 0; tap < 3; tap++)
                        for (int kc = 0; kc < 8; kc++) {
                            const __half* inp = (const __half*)(smem + offI + ((size_t)(kc * rI + r + tap) * 16));
                            float xv[8];
                            for (int t = 0; t < 8; t++) xv[t] = __half2float(inp[t]);
                            const __half* wp = wl + tap * 4096 + kc * 512;
                            for (int o = 0; o < CH; o++)
                                for (int t = 0; t < 8; t++)
                                    acc[o] += xv[t] * __half2float(wp[o * 8 + t]);
                        }
                }
                for (int o = 0; o < CH; o++) {
                    float v = 0.f;
                    if (!zero) {
                        v = acc[o];
                        if (layer < 2) v = fmaxf(v + sBias[layer * 64 + o], 0.f);
                    }
                    *(__half*)(smem + offO + ((size_t)((o >> 3) * rO + r) * 16) + (o & 7) * 2) = __float2half(v);
                }
            }
            __syncthreads();
        }
        // combine + scatter
        for (int it = tid; it < TILE * 8; it += NTHREADS) {
            int r = it >> 3, c = it & 7;
            if (tile0 + r >= NPTS) continue;
            int dst = sS[r];
            const __half* hp = (const __half*)(smem + OFF_B1 + (size_t)(c * R_B1 + r) * 16);
            const __half* rp = (const __half*)(smem + OFF_IN0 + (size_t)(c * R_IN + r + 3) * 16);
            for (int t = 0; t < 8; t++) {
                float y = fmaxf(__half2float(rp[t]) + __half2float(hp[t]) + sBias[128 + c * 8 + t], 0.f);
                if (outHalf) xout16[((size_t)b * NPTS + dst) * CH + c * 8 + t] = __float2half(y);
                else         xout32[((size_t)b * NPTS + dst) * CH + c * 8 + t] = y;
            }
        }
        __syncthreads();
    }
#endif
}

// ---------------------------------------------------------------------------
// Launch
// ---------------------------------------------------------------------------
extern "C" void kernel_launch(void* const* d_in, const int* in_sizes, int n_in,
                              void* d_out, int out_size) {
    const float* x      = (const float*)d_in[0];
    const void*  pa1    = d_in[1];
    const void*  pa2    = d_in[3];
    const void*  re2    = d_in[4];
    const float* conv_w = (const float*)d_in[5];
    const float* gma    = (const float*)d_in[6];
    const float* bta    = (const float*)d_in[7];
    const float* mean   = (const float*)d_in[8];
    const float* var    = (const float*)d_in[9];

    __half* mid;  cudaGetSymbolAddress((void**)&mid,  g_mid);
    __half* wh;   cudaGetSymbolAddress((void**)&wh,   g_wh);
    float*  bias; cudaGetSymbolAddress((void**)&bias, g_bias);
    int*    comp; cudaGetSymbolAddress((void**)&comp, g_comp);
    int*    ctr;  cudaGetSymbolAddress((void**)&ctr,  g_ctr);

    int nsm = 148;
    cudaDeviceGetAttribute(&nsm, cudaDevAttrMultiProcessorCount, 0);

    cudaFuncSetAttribute(block_kernel, cudaFuncAttributeMaxDynamicSharedMemorySize, SMEM_BYTES);

    detect_idx_kernel<<<1, 256>>>((const unsigned int*)pa1);
    repack_kernel<<<(NBLK * 3 * CH * CH + 255) / 256, 256>>>(conv_w, gma, bta, mean, var);
    compose_kernel<<<(NBATCH * NPTS + 255) / 256, 256>>>(pa1, re2);

    // block 1: x(fp32) --(gather pa1, cvt fp16)--> conv --(scatter comp)--> mid(fp16, block2-gather order)
    block_kernel<<<nsm, NTHREADS, SMEM_BYTES>>>(x, nullptr, nullptr, mid, 1,
                                                pa1, 0, comp, 0, wh, bias, ctr);
    // block 2: mid(fp16) --(linear gather)--> conv --(scatter pa2)--> out(fp32)
    block_kernel<<<nsm, NTHREADS, SMEM_BYTES>>>(nullptr, mid, (float*)d_out, nullptr, 0,
                                                nullptr, 1, pa2, 1, wh + 36864,
                                                bias + 3 * CH, ctr + 1);
}

// round 14
// speedup vs baseline: 1.4933x; 1.0463x over previous
#include <cuda_runtime.h>
#include <cuda_fp16.h>
#include <cstdint>
#include <cstddef>

// tcgen05 is arch-SPECIFIC: only on the sm_103a pass; plain compute_103 gets a fallback.
#if defined(__CUDA_ARCH__) && (defined(__CUDA_ARCH_FEAT_SM103_ALL) || defined(__CUDA_ARCH_FEAT_SM100_ALL) || defined(__CUDA_ARCH_FEAT_SM101_ALL))
#define HAS_TC 1
#else
#define HAS_TC 0
#endif

// Problem constants
#define NBATCH   2
#define CH       64
#define NPTS     262144
#define NBLK     2

// Tiling (M=256 TMEM limit: R_IN must be <= 256)
#define TILE     248
#define R_IN     254
#define R_B1     252
#define R_B2     250
#define NTHREADS 512
#define GRID_X   ((NPTS + TILE - 1) / TILE)   // 1058
#define NWORK    (GRID_X * NBATCH)            // 2116

// SMEM layout (fp16 activations). Canonical K-major chunks: 16B unit = 8 fp16
// channels; addr = chunk*ROWS*16 + row*16. 8 chunks cover CH=64.
#define BUF_SZ    (R_IN * 128)                   // 32512
#define OFF_IN0   0
#define OFF_IN1   BUF_SZ
#define OFF_B1    (2 * BUF_SZ)
#define OFF_W     (3 * BUF_SZ)                   // 97536 (3 resident slabs x 24576B)
#define OFF_BIAS  (OFF_W + 73728)                // 171264 (3 x 64 floats)
#define OFF_IDXG0 (OFF_BIAS + 768)               // 254 ints, padded 1024
#define OFF_IDXG1 (OFF_IDXG0 + 1024)
#define OFF_IDXS0 (OFF_IDXG1 + 1024)             // 248 ints, padded 1024
#define OFF_IDXS1 (OFF_IDXS0 + 1024)
#define OFF_TM    (OFF_IDXS1 + 1024)
#define OFF_MBAR  (OFF_TM + 16)                  // 4 mbarriers: A0,A1,B0,B1 (8B each)
#define OFF_WORK  (OFF_MBAR + 32)
#define SMEM_BYTES (OFF_WORK + 16)               // ~176 KB

// idesc kind::f16: D=f32(1<<4), A=B=FP16(0), N=64 (8<<17), M=128 (8<<24)
#define IDESC_F16 0x08100010u

// Device scratch
__device__ __half g_mid[(size_t)NBATCH * NPTS * CH];   // inter-block activations, fp16
__device__ __half g_wh[NBLK * 3 * 3 * 8 * 64 * 8];     // [bl(6)][tap][kc8][o64][i%8], BN-folded fp16
__device__ float  g_bias[NBLK * 3 * CH];
__device__ int    g_comp[NBATCH * NPTS];               // composed scatter idx for block 1
__device__ int    g_ctr[2];                            // work-stealing counters
__device__ int    g_is64;

__device__ __forceinline__ uint32_t smem_u32(const void* p) {
    uint32_t a;
    asm("{ .reg .u64 t; cvta.to.shared.u64 t, %1; cvt.u32.u64 %0, t; }" : "=r"(a) : "l"(p));
    return a;
}

// cp.async 16B with zero-fill when invalid (src-size 0)
__device__ __forceinline__ void cp16(uint32_t dst, const void* src, int valid) {
    int sz = valid ? 16 : 0;
    asm volatile("cp.async.cg.shared.global [%0], [%1], 16, %2;" :: "r"(dst), "l"(src), "r"(sz) : "memory");
}
#define CP_COMMIT() asm volatile("cp.async.commit_group;" ::: "memory")
#define CP_WAIT0()  asm volatile("cp.async.wait_group 0;" ::: "memory")

__device__ __forceinline__ uint32_t packh2(float a, float b) {
    __half2 h = __floats2half2_rn(a, b);
    return *(uint32_t*)&h;
}

#if HAS_TC
// ---------------------------------------------------------------------------
__device__ __forceinline__ uint32_t elect_one() {
    uint32_t p;
    asm volatile("{\n\t.reg .pred p;\n\telect.sync _|p, 0xFFFFFFFF;\n\tselp.b32 %0, 1, 0, p;\n\t}" : "=r"(p));
    return p;
}
#define TCGEN05_ALLOC(sl, n)  asm volatile("tcgen05.alloc.cta_group::1.sync.aligned.shared::cta.b32 [%0], %1;" :: "r"(sl), "r"((uint32_t)(n)) : "memory")
#define TCGEN05_DEALLOC(t, n) asm volatile("tcgen05.dealloc.cta_group::1.sync.aligned.b32 %0, %1;" :: "r"(t), "r"((uint32_t)(n)))
#define TCGEN05_RELINQ()      asm volatile("tcgen05.relinquish_alloc_permit.cta_group::1.sync.aligned;")
#define TCGEN05_COMMIT(mb)    asm volatile("tcgen05.commit.cta_group::1.mbarrier::arrive::one.shared::cluster.b64 [%0];" :: "r"(mb) : "memory")
#define TCGEN05_WAIT_LD()     asm volatile("tcgen05.wait::ld.sync.aligned;" ::: "memory")
#define TCGEN05_FENCE_AFTER() asm volatile("tcgen05.fence::after_thread_sync;" ::: "memory")
#define TCGEN05_FENCE_BEFORE() asm volatile("tcgen05.fence::before_thread_sync;" ::: "memory")
#define FENCE_ASYNC()         asm volatile("fence.proxy.async.shared::cta;" ::: "memory")
#define MBAR_INIT(mb, n)      asm volatile("mbarrier.init.shared.b64 [%0], %1;" :: "r"(mb), "r"((uint32_t)(n)) : "memory")

#define MBAR_WAIT(mb, ph) do {                                                   \
    uint32_t _m = (mb), _p = (ph), _d;                                           \
    asm volatile("{\n\t.reg .pred p;\n\t"                                        \
        "mbarrier.try_wait.parity.acquire.cta.shared::cta.b64 p, [%1], %2;\n\t"  \
        "selp.b32 %0, 1, 0, p;\n\t}" : "=r"(_d) : "r"(_m), "r"(_p) : "memory");  \
    if (!_d) {                                                                   \
        asm volatile("{\n\t.reg .pred P1;\n\t"                                   \
        "WL_%=:\n\t"                                                             \
        "mbarrier.try_wait.parity.acquire.cta.shared::cta.b64 P1, [%0], %1, 0x989680;\n\t" \
        "@P1 bra.uni WD_%=;\n\t"                                                 \
        "bra.uni WL_%=;\n\t"                                                     \
        "WD_%=:\n\t}" :: "r"(_m), "r"(_p) : "memory");                           \
    }                                                                            \
} while (0)

#define LDTM_X32(r, addr) \
    asm volatile("tcgen05.ld.sync.aligned.32x32b.x32.b32 " \
        "{%0, %1, %2, %3, %4, %5, %6, %7, " \
        " %8, %9, %10, %11, %12, %13, %14, %15, " \
        " %16, %17, %18, %19, %20, %21, %22, %23, " \
        " %24, %25, %26, %27, %28, %29, %30, %31}, [%32];" \
        : "=r"((r)[0]),  "=r"((r)[1]),  "=r"((r)[2]),  "=r"((r)[3]), \
          "=r"((r)[4]),  "=r"((r)[5]),  "=r"((r)[6]),  "=r"((r)[7]), \
          "=r"((r)[8]),  "=r"((r)[9]),  "=r"((r)[10]), "=r"((r)[11]), \
          "=r"((r)[12]), "=r"((r)[13]), "=r"((r)[14]), "=r"((r)[15]), \
          "=r"((r)[16]), "=r"((r)[17]), "=r"((r)[18]), "=r"((r)[19]), \
          "=r"((r)[20]), "=r"((r)[21]), "=r"((r)[22]), "=r"((r)[23]), \
          "=r"((r)[24]), "=r"((r)[25]), "=r"((r)[26]), "=r"((r)[27]), \
          "=r"((r)[28]), "=r"((r)[29]), "=r"((r)[30]), "=r"((r)[31]) \
        : "r"(addr))

__device__ __forceinline__ void mma_f16(uint32_t d, uint64_t ad, uint64_t bd, uint32_t en) {
    asm volatile("{\n\t.reg .pred p;\n\tsetp.ne.u32 p, %4, 0;\n\t"
        "tcgen05.mma.cta_group::1.kind::f16 [%0], %1, %2, %3, {%5, %5, %5, %5}, p;\n\t}"
        :: "r"(d), "l"(ad), "l"(bd), "r"(IDESC_F16), "r"(en), "r"(0u) : "memory");
}

__device__ __forceinline__ uint64_t make_desc(uint32_t addr, uint32_t lbo, uint32_t sbo) {
    uint64_t d = (uint64_t)((addr >> 4) & 0x3FFF);
    d |= (uint64_t)(lbo & 0x3FFF) << 16;
    d |= (uint64_t)(sbo & 0x3FFF) << 32;
    d |= (uint64_t)1 << 46;
    return d;
}

// One conv layer (fp16, K=64 in 4 k-steps of 16); commits tile T to mbarBase+T*8.
__device__ __forceinline__ void issue_conv(uint32_t aAddr, int aLBO, uint32_t wAddr,
                                           uint32_t tmemD, uint32_t mbarBase) {
    uint64_t ab = make_desc(aAddr, aLBO, 8);
    uint64_t bb = make_desc(wAddr, 64, 8);
#pragma unroll
    for (int T = 0; T < 2; T++) {
        uint32_t en = 0;
#pragma unroll
        for (int tap = 0; tap < 3; tap++)
#pragma unroll
            for (int ks = 0; ks < 4; ks++) {
                mma_f16(tmemD + T * 64,
                        ab + (uint64_t)(T * 128 + tap + 2 * ks * aLBO),
                        bb + (uint64_t)(tap * 512 + 2 * ks * 64), en);
                en = 1;
            }
        TCGEN05_COMMIT(mbarBase + T * 8);
    }
}
#endif // HAS_TC

// ---------------------------------------------------------------------------
// Gather one tile into fp16 canonical smem. Block 1: LDG fp32 + convert + STS.
// Block 2 (linearGather): cp.async 16B from fp16 mid.
// ---------------------------------------------------------------------------
__device__ __forceinline__ void gather_tile(char* smem, uint32_t sbase, int dstOff,
                                            const float* xin32, const __half* xin16,
                                            int linearGather, int bn, int tn,
                                            const int* sG, int tid) {
    if (linearGather) {
        const __half* xb = xin16 + (size_t)bn * NPTS * CH;
        for (int it = tid; it < R_IN * 8; it += NTHREADS) {
            int r = it >> 3, c = it & 7;
            int p = tn - 3 + r;
            int valid = (p >= 0) && (p < NPTS);
            int pc = valid ? p : 0;
            cp16(sbase + dstOff + (uint32_t)(c * R_IN + r) * 16,
                 xb + (size_t)pc * CH + c * 8, valid);
        }
    } else {
        const float* xb = xin32 + (size_t)bn * NPTS * CH;
        for (int it = tid; it < R_IN * 8; it += NTHREADS) {
            int r = it >> 3, c = it & 7;
            int src = sG[r];
            uint4 u = make_uint4(0u, 0u, 0u, 0u);
            if (src >= 0) {
                const float* sp = xb + (size_t)src * CH + c * 8;
                float4 a = *(const float4*)sp;
                float4 b2 = *(const float4*)(sp + 4);
                u.x = packh2(a.x, a.y);  u.y = packh2(a.z, a.w);
                u.z = packh2(b2.x, b2.y); u.w = packh2(b2.z, b2.w);
            }
            *(uint4*)(smem + dstOff + (size_t)(c * R_IN + r) * 16) = u;
        }
    }
}

// ---------------------------------------------------------------------------
// Prep kernels
// ---------------------------------------------------------------------------
__global__ void detect_idx_kernel(const unsigned int* __restrict__ w) {
    __shared__ int any;
    if (threadIdx.x == 0) { any = 0; g_ctr[0] = 0; g_ctr[1] = 0; }
    __syncthreads();
    int local = 0;
    for (int i = threadIdx.x; i < 2048; i += blockDim.x)
        if (w[2 * i + 1] != 0u) local = 1;
    if (local) atomicOr(&any, 1);
    __syncthreads();
    if (threadIdx.x == 0) g_is64 = any ? 0 : 1;
}

// Fold BN into W; pack fp16 canonical B layout [bl][tap][kc][o][i%8].
__global__ void repack_kernel(const float* __restrict__ w,
                              const float* __restrict__ gm,
                              const float* __restrict__ bt,
                              const float* __restrict__ mn,
                              const float* __restrict__ vr) {
    int idx = blockIdx.x * blockDim.x + threadIdx.x;
    if (idx >= NBLK * 3 * CH * CH) return;
    int i  = idx & 63;
    int o  = (idx >> 6) & 63;
    int bl = idx >> 12;
    float scale = gm[bl * CH + o] * rsqrtf(vr[bl * CH + o] + 1e-5f);
#pragma unroll
    for (int t = 0; t < 3; t++) {
        float val = w[(((size_t)bl * CH + o) * CH + i) * 3 + t] * scale;
        g_wh[(size_t)bl * 12288 + t * 4096 + (i >> 3) * 512 + o * 8 + (i & 7)] = __float2half(val);
    }
    if (i == 0)
        g_bias[bl * CH + o] = bt[bl * CH + o] - mn[bl * CH + o] * scale;
}

// comp[b][p] = re2[b][ pa1[b][p] ]
__global__ void compose_kernel(const void* __restrict__ pa1, const void* __restrict__ re2) {
    int idx = blockIdx.x * blockDim.x + threadIdx.x;
    if (idx >= NBATCH * NPTS) return;
    int b = idx / NPTS;
    int is64 = g_is64;
    long long v1 = is64 ? ((const long long*)pa1)[idx] : (long long)((const int*)pa1)[idx];
    size_t j = (size_t)b * NPTS + (size_t)v1;
    int v2 = is64 ? (int)((const long long*)re2)[j] : ((const int*)re2)[j];
    g_comp[idx] = v2;
}

// ---------------------------------------------------------------------------
// Persistent fused block kernel (fp16 tcgen05), work stealing, resident weights.
// Split mbarriers: A (conv1 commits) / B (conv2+conv3 commits) -- each wait has
// at most ONE outstanding flip, so the early conv1-next pre-issue cannot alias
// mbarrier parity (the round-12 deadlock).
// ---------------------------------------------------------------------------
__global__ __launch_bounds__(NTHREADS, 1)
void block_kernel(const float* __restrict__ xin32, const __half* __restrict__ xin16,
                  float* __restrict__ xout32, __half* __restrict__ xout16, int outHalf,
                  const void* __restrict__ gIdx, int linearGather,
                  const void* __restrict__ scIdx, int scMode,
                  const __half* __restrict__ wslabH, const float* __restrict__ bias,
                  int* __restrict__ ctr) {
    extern __shared__ char smem[];
    const int tid  = threadIdx.x;
    const int warp = tid >> 5;
    const int lane = tid & 31;
    const int is64  = g_is64;
    const int sIs64 = scMode ? is64 : 0;

    const uint32_t sbase = smem_u32(smem);
    float* sBias = (float*)(smem + OFF_BIAS);
    int*   sWrk  = (int*)(smem + OFF_WORK);

    const int inOff[2]   = {OFF_IN0, OFF_IN1};
    const int idxGOff[2] = {OFF_IDXG0, OFF_IDXG1};
    const int idxSOff[2] = {OFF_IDXS0, OFF_IDXS1};

#if HAS_TC
    const uint32_t mbarA = sbase + OFF_MBAR;        // conv1 commits (per tile)
    const uint32_t mbarB = sbase + OFF_MBAR + 16;   // conv2+conv3 commits (per tile)
    if (tid == 0) {
        MBAR_INIT(mbarA, 1);     MBAR_INIT(mbarA + 8, 1);
        MBAR_INIT(mbarB, 1);     MBAR_INIT(mbarB + 8, 1);
    }
    if (warp == 0) {
        TCGEN05_ALLOC(sbase + OFF_TM, 256);
        TCGEN05_RELINQ();
    }
#endif

    // steal first work + bias + ALL 3 weight slabs (resident)
    if (tid == 0) sWrk[0] = atomicAdd(ctr, 1);
    if (tid < 3 * CH) sBias[tid] = bias[tid];
#pragma unroll
    for (int k = 0; k < 9; k++)
        ((uint4*)(smem + OFF_W))[tid + k * NTHREADS] = ((const uint4*)wslabH)[tid + k * NTHREADS];
    __syncthreads();
    int work = sWrk[0];
    if (tid == 0) sWrk[0] = (work < NWORK) ? atomicAdd(ctr, 1) : NWORK;  // steal-ahead

    // ---- prologue: idx + gather for first work ----
    if (work < NWORK) {
        int b0 = work / GRID_X, t0 = (work % GRID_X) * TILE;
        int* sG = (int*)(smem + OFF_IDXG0);
        int* sS = (int*)(smem + OFF_IDXS0);
        if (!linearGather) {
            for (int r = tid; r < R_IN; r += NTHREADS) {
                int p = t0 - 3 + r;
                int v = -1;
                if (p >= 0 && p < NPTS) {
                    size_t gp = (size_t)b0 * NPTS + p;
                    v = is64 ? (int)((const long long*)gIdx)[gp] : ((const int*)gIdx)[gp];
                }
                sG[r] = v;
            }
        }
        for (int r = tid; r < TILE; r += NTHREADS) {
            int p = t0 + r;
            int v = 0;
            if (p < NPTS) {
                size_t gp = (size_t)b0 * NPTS + p;
                v = sIs64 ? (int)((const long long*)scIdx)[gp] : ((const int*)scIdx)[gp];
            }
            sS[r] = v;
        }
        __syncthreads();
        gather_tile(smem, sbase, OFF_IN0, xin32, xin16, linearGather, b0, t0, sG, tid);
    }
    CP_COMMIT();

#if HAS_TC
    uint32_t tmem;
    asm volatile("ld.shared.b32 %0, [%1];" : "=r"(tmem) : "r"(sbase + OFF_TM));

    CP_WAIT0();
    TCGEN05_FENCE_BEFORE();
    FENCE_ASYNC();
    __syncthreads();
    if (work < NWORK && warp == 0 && elect_one())
        issue_conv(sbase + OFF_IN0, R_IN, sbase + OFF_W, tmem, mbarA);
    int wnext = sWrk[0];

    // Warp mapping: tile = w>>3, colhalf = (w>>2)&1, subpartition = w&3
    const int mtile = warp >> 3;
    const int colh  = (warp >> 2) & 1;
    const int myrow = mtile * 128 + (warp & 3) * 32 + lane;
    const uint32_t myA = mbarA + mtile * 8;
    const uint32_t myB = mbarB + mtile * 8;
    const uint32_t otB = mbarB + (1 - mtile) * 8;

    int phA = 0, phB = 0, cur = 0, treg = 0;
    while (work < NWORK) {
        const int b     = work / GRID_X;
        const int tile0 = (work % GRID_X) * TILE;
        const int nxt   = cur ^ 1;
        char* INp = smem + inOff[cur];
        int* sG_n = (int*)(smem + idxGOff[nxt]);
        int* sS_c = (int*)(smem + idxSOff[cur]);
        int* sS_n = (int*)(smem + idxSOff[nxt]);
        const uint32_t dreg  = tmem + treg * 128;
        const uint32_t dregN = tmem + (treg ^ 1) * 128;
        const uint32_t dcol  = dreg + mtile * 64 + colh * 32;

        // ===== phase 1: conv1 in flight (pre-issued last iteration / prologue) =====
        if (wnext < NWORK) {   // next-work indices under conv1
            int bn = wnext / GRID_X, tn = (wnext % GRID_X) * TILE;
            if (!linearGather) {
                for (int r = tid; r < R_IN; r += NTHREADS) {
                    int p = tn - 3 + r;
                    int v = -1;
                    if (p >= 0 && p < NPTS) {
                        size_t gp = (size_t)bn * NPTS + p;
                        v = is64 ? (int)((const long long*)gIdx)[gp] : ((const int*)gIdx)[gp];
                    }
                    sG_n[r] = v;
                }
            }
            for (int r = tid; r < TILE; r += NTHREADS) {
                int p = tn + r;
                int v = 0;
                if (p < NPTS) {
                    size_t gp = (size_t)bn * NPTS + p;
                    v = sIs64 ? (int)((const long long*)scIdx)[gp] : ((const int*)scIdx)[gp];
                }
                sS_n[r] = v;
            }
        }

        MBAR_WAIT(myA, phA);             // conv1 (own tile) done; also implies prior convs drained
        phA ^= 1;
        TCGEN05_FENCE_AFTER();
        {
            uint32_t rg[32];
            LDTM_X32(rg, dcol);
            TCGEN05_WAIT_LD();
            int r = myrow, p = tile0 - 2 + r;
            if (r < R_B1) {
                bool zero = (p < 0) || (p >= NPTS);
                const float* bb = sBias + colh * 32;
#pragma unroll
                for (int k = 0; k < 4; k++) {
                    uint4 u = make_uint4(0u, 0u, 0u, 0u);
                    if (!zero) {
#pragma unroll
                        for (int t = 0; t < 4; t++) {
                            float a = fmaxf(__uint_as_float(rg[8 * k + 2 * t]) + bb[8 * k + 2 * t], 0.f);
                            float c2 = fmaxf(__uint_as_float(rg[8 * k + 2 * t + 1]) + bb[8 * k + 2 * t + 1], 0.f);
                            ((uint32_t*)&u)[t] = packh2(a, c2);
                        }
                    }
                    *(uint4*)(smem + OFF_B1 + ((size_t)(colh * 4 + k) * R_B1 + r) * 16) = u;
                }
            }
        }
        TCGEN05_FENCE_BEFORE();
        FENCE_ASYNC();
        __syncthreads();

        // ===== phase 2: conv2 (epilogue rewrites B1 in R_B2 layout) =====
        if (warp == 0 && elect_one())
            issue_conv(sbase + OFF_B1, R_B1, sbase + OFF_W + 24576, dreg, mbarB);
        if (tid == 0) sWrk[0] = (wnext < NWORK) ? atomicAdd(ctr, 1) : NWORK;

        if (wnext < NWORK) {   // next-work gather under conv2
            int bn = wnext / GRID_X, tn = (wnext % GRID_X) * TILE;
            gather_tile(smem, sbase, inOff[nxt], xin32, xin16, linearGather, bn, tn, sG_n, tid);
        }
        CP_COMMIT();

        MBAR_WAIT(myB, phB);
        TCGEN05_FENCE_AFTER();
        {
            uint32_t rg2[32];
            LDTM_X32(rg2, dcol);
            MBAR_WAIT(otB, phB);     // ALL conv2 MMAs done reading B1 (hidden under LDTM)
            TCGEN05_WAIT_LD();
            int r = myrow, p = tile0 - 1 + r;
            if (r < R_B2) {
                bool zero = (p < 0) || (p >= NPTS);
                const float* bb = sBias + 64 + colh * 32;
#pragma unroll
                for (int k = 0; k < 4; k++) {
                    uint4 u = make_uint4(0u, 0u, 0u, 0u);
                    if (!zero) {
#pragma unroll
                        for (int t = 0; t < 4; t++) {
                            float a = fmaxf(__uint_as_float(rg2[8 * k + 2 * t]) + bb[8 * k + 2 * t], 0.f);
                            float c2 = fmaxf(__uint_as_float(rg2[8 * k + 2 * t + 1]) + bb[8 * k + 2 * t + 1], 0.f);
                            ((uint32_t*)&u)[t] = packh2(a, c2);
                        }
                    }
                    *(uint4*)(smem + OFF_B1 + ((size_t)(colh * 4 + k) * R_B2 + r) * 16) = u;
                }
            }
        }
        phB ^= 1;
        TCGEN05_FENCE_BEFORE();
        FENCE_ASYNC();
        __syncthreads();

        // ===== phase 3: conv3 (-> mbarB); pre-issue next conv1 (-> mbarA) =====
        if (warp == 0 && elect_one())
            issue_conv(sbase + OFF_B1, R_B2, sbase + OFF_W + 49152, dreg, mbarB);

        CP_WAIT0();                      // next gather landed
        TCGEN05_FENCE_BEFORE();
        FENCE_ASYNC();
        __syncthreads();                 // IN[nxt] visible to async proxy, all threads
        if (wnext < NWORK && warp == 0 && elect_one())
            issue_conv(sbase + inOff[nxt], R_IN, sbase + OFF_W, dregN, mbarA);

        MBAR_WAIT(myB, phB);             // own conv3 tile done (B barrier: no aliasing)
        phB ^= 1;
        TCGEN05_FENCE_AFTER();

        {   // epilogue 3 under next work's conv1
            uint32_t rg[32];
            LDTM_X32(rg, dcol);
            TCGEN05_WAIT_LD();
            int r = myrow;
            bool go = (r < TILE) && (tile0 + r < NPTS);
            if (go) {
                int dst = sS_c[r];
                const float* bb = sBias + 128 + colh * 32;
#pragma unroll
                for (int k = 0; k < 4; k++) {
                    uint4 rv = *(const uint4*)(INp + ((size_t)(colh * 4 + k) * R_IN + (r + 3)) * 16);
                    float y[8];
#pragma unroll
                    for (int t = 0; t < 4; t++) {
                        __half2 hh = *(__half2*)(((uint32_t*)&rv) + t);
                        float2 rf = __half22float2(hh);
                        y[2 * t]     = fmaxf(rf.x + __uint_as_float(rg[8 * k + 2 * t])     + bb[8 * k + 2 * t], 0.f);
                        y[2 * t + 1] = fmaxf(rf.y + __uint_as_float(rg[8 * k + 2 * t + 1]) + bb[8 * k + 2 * t + 1], 0.f);
                    }
                    if (outHalf) {
                        uint4 u;
                        u.x = packh2(y[0], y[1]); u.y = packh2(y[2], y[3]);
                        u.z = packh2(y[4], y[5]); u.w = packh2(y[6], y[7]);
                        *(uint4*)(xout16 + ((size_t)b * NPTS + dst) * CH + (colh * 4 + k) * 8) = u;
                    } else {
                        float* op = xout32 + ((size_t)b * NPTS + dst) * CH + colh * 32 + 8 * k;
                        *(float4*)op       = make_float4(y[0], y[1], y[2], y[3]);
                        *(float4*)(op + 4) = make_float4(y[4], y[5], y[6], y[7]);
                    }
                }
            }
        }
        TCGEN05_FENCE_BEFORE();
        __syncthreads();

        work = wnext;
        wnext = sWrk[0];
        cur ^= 1;
        treg ^= 1;
    }
    if (warp == 0) TCGEN05_DEALLOC(tmem, 256);

#else // ---- scalar fp16 fallback (compute_103 JIT image only) ----
    CP_WAIT0();
    __syncthreads();
    const __half* sWh = (const __half*)(smem + OFF_W);
    for (int w2 = blockIdx.x; w2 < NWORK; w2 += gridDim.x) {
        const int b     = w2 / GRID_X;
        const int tile0 = (w2 % GRID_X) * TILE;
        int* sG = (int*)(smem + OFF_IDXG0);
        int* sS = (int*)(smem + OFF_IDXS0);
        __syncthreads();
        if (!linearGather) {
            for (int r = tid; r < R_IN; r += NTHREADS) {
                int p = tile0 - 3 + r;
                int v = -1;
                if (p >= 0 && p < NPTS) {
                    size_t gp = (size_t)b * NPTS + p;
                    v = is64 ? (int)((const long long*)gIdx)[gp] : ((const int*)gIdx)[gp];
                }
                sG[r] = v;
            }
        }
        for (int r = tid; r < TILE; r += NTHREADS) {
            int p = tile0 + r;
            int v = 0;
            if (p < NPTS) {
                size_t gp = (size_t)b * NPTS + p;
                v = sIs64 ? (int)((const long long*)scIdx)[gp] : ((const int*)scIdx)[gp];
            }
            sS[r] = v;
        }
        __syncthreads();
        for (int it = tid; it < R_IN * 8; it += NTHREADS) {
            int r = it >> 3, c = it & 7;
            uint4 u = make_uint4(0u, 0u, 0u, 0u);
            if (linearGather) {
                int p = tile0 - 3 + r;
                if (p >= 0 && p < NPTS)
                    u = *(const uint4*)(xin16 + ((size_t)b * NPTS + p) * CH + c * 8);
            } else {
                int src = sG[r];
                if (src >= 0) {
                    const float* sp = xin32 + ((size_t)b * NPTS + src) * CH + c * 8;
                    float4 a = *(const float4*)sp, b2 = *(const float4*)(sp + 4);
                    u.x = packh2(a.x, a.y);  u.y = packh2(a.z, a.w);
                    u.z = packh2(b2.x, b2.y); u.w = packh2(b2.z, b2.w);
                }
            }
            *(uint4*)(smem + OFF_IN0 + (size_t)(c * R_IN + r) * 16) = u;
        }
        __syncthreads();
        for (int layer = 0; layer < 3; layer++) {
            int offI = (layer == 0) ? OFF_IN0 : (layer == 1) ? OFF_B1 : OFF_IN1;
            int rI   = (layer == 0) ? R_IN : (layer == 1) ? R_B1 : R_B2;
            int offO = (layer == 1) ? OFF_IN1 : OFF_B1;
            int rO   = (layer == 0) ? R_B1 : (layer == 1) ? R_B2 : R_B1;
            int live = (layer == 0) ? R_B1 : (layer == 1) ? R_B2 : TILE;
            int pb   = tile0 - 2 + layer;
            const __half* wl = sWh + layer * 12288;
            for (int r = tid; r < live; r += NTHREADS) {
                float acc[CH];
#pragma unroll
                for (int o = 0; o < CH; o++) acc[o] = 0.f;
                bool zero = (pb + r < 0) || (pb + r >= NPTS);
                if (!zero) {
                    for (int tap = 0; tap < 3; tap++)
                        for (int kc = 0; kc < 8; kc++) {
                            const __half* inp = (const __half*)(smem + offI + ((size_t)(kc * rI + r + tap) * 16));
                            float xv[8];
                            for (int t = 0; t < 8; t++) xv[t] = __half2float(inp[t]);
                            const __half* wp = wl + tap * 4096 + kc * 512;
                            for (int o = 0; o < CH; o++)
                                for (int t = 0; t < 8; t++)
                                    acc[o] += xv[t] * __half2float(wp[o * 8 + t]);
                        }
                }
                for (int o = 0; o < CH; o++) {
                    float v = 0.f;
                    if (!zero) {
                        v = acc[o];
                        if (layer < 2) v = fmaxf(v + sBias[layer * 64 + o], 0.f);
                    }
                    *(__half*)(smem + offO + ((size_t)((o >> 3) * rO + r) * 16) + (o & 7) * 2) = __float2half(v);
                }
            }
            __syncthreads();
        }
        for (int it = tid; it < TILE * 8; it += NTHREADS) {
            int r = it >> 3, c = it & 7;
            if (tile0 + r >= NPTS) continue;
            int dst = sS[r];
            const __half* hp = (const __half*)(smem + OFF_B1 + (size_t)(c * R_B1 + r) * 16);
            const __half* rp = (const __half*)(smem + OFF_IN0 + (size_t)(c * R_IN + r + 3) * 16);
            for (int t = 0; t < 8; t++) {
                float y = fmaxf(__half2float(rp[t]) + __half2float(hp[t]) + sBias[128 + c * 8 + t], 0.f);
                if (outHalf) xout16[((size_t)b * NPTS + dst) * CH + c * 8 + t] = __float2half(y);
                else         xout32[((size_t)b * NPTS + dst) * CH + c * 8 + t] = y;
            }
        }
        __syncthreads();
    }
#endif
}

// ---------------------------------------------------------------------------
// Launch
// ---------------------------------------------------------------------------
extern "C" void kernel_launch(void* const* d_in, const int* in_sizes, int n_in,
                              void* d_out, int out_size) {
    const float* x      = (const float*)d_in[0];
    const void*  pa1    = d_in[1];
    const void*  pa2    = d_in[3];
    const void*  re2    = d_in[4];
    const float* conv_w = (const float*)d_in[5];
    const float* gma    = (const float*)d_in[6];
    const float* bta    = (const float*)d_in[7];
    const float* mean   = (const float*)d_in[8];
    const float* var    = (const float*)d_in[9];

    __half* mid;  cudaGetSymbolAddress((void**)&mid,  g_mid);
    __half* wh;   cudaGetSymbolAddress((void**)&wh,   g_wh);
    float*  bias; cudaGetSymbolAddress((void**)&bias, g_bias);
    int*    comp; cudaGetSymbolAddress((void**)&comp, g_comp);
    int*    ctr;  cudaGetSymbolAddress((void**)&ctr,  g_ctr);

    int nsm = 148;
    cudaDeviceGetAttribute(&nsm, cudaDevAttrMultiProcessorCount, 0);

    cudaFuncSetAttribute(block_kernel, cudaFuncAttributeMaxDynamicSharedMemorySize, SMEM_BYTES);

    detect_idx_kernel<<<1, 256>>>((const unsigned int*)pa1);
    repack_kernel<<<(NBLK * 3 * CH * CH + 255) / 256, 256>>>(conv_w, gma, bta, mean, var);
    compose_kernel<<<(NBATCH * NPTS + 255) / 256, 256>>>(pa1, re2);

    // block 1: x(fp32) --(gather pa1, cvt fp16)--> conv --(scatter comp)--> mid(fp16, block2-gather order)
    block_kernel<<<nsm, NTHREADS, SMEM_BYTES>>>(x, nullptr, nullptr, mid, 1,
                                                pa1, 0, comp, 0, wh, bias, ctr);
    // block 2: mid(fp16) --(linear gather)--> conv --(scatter pa2)--> out(fp32)
    block_kernel<<<nsm, NTHREADS, SMEM_BYTES>>>(nullptr, mid, (float*)d_out, nullptr, 0,
                                                nullptr, 1, pa2, 1, wh + 36864,
                                                bias + 3 * CH, ctr + 1);
}

// round 16
// speedup vs baseline: 1.5187x; 1.0170x over previous
#include <cuda_runtime.h>
#include <cuda_fp16.h>
#include <cstdint>
#include <cstddef>

// tcgen05 is arch-SPECIFIC: only on the sm_103a pass; plain compute_103 gets a fallback.
#if defined(__CUDA_ARCH__) && (defined(__CUDA_ARCH_FEAT_SM103_ALL) || defined(__CUDA_ARCH_FEAT_SM100_ALL) || defined(__CUDA_ARCH_FEAT_SM101_ALL))
#define HAS_TC 1
#else
#define HAS_TC 0
#endif

// Problem constants
#define NBATCH   2
#define CH       64
#define NPTS     262144
#define NBLK     2

// Tiling (M=256 TMEM limit: R_IN must be <= 256)
#define TILE     248
#define R_IN     254
#define R_B1     252
#define R_B2     250
#define NTHREADS 512
#define GRID_X   ((NPTS + TILE - 1) / TILE)   // 1058
#define NWORK    (GRID_X * NBATCH)            // 2116

// SMEM layout (fp16 activations). Canonical K-major chunks: 16B unit = 8 fp16
// channels; addr = chunk*ROWS*16 + row*16. 8 chunks cover CH=64.
#define BUF_SZ    (R_IN * 128)                   // 32512
#define OFF_IN0   0
#define OFF_IN1   BUF_SZ
#define OFF_B1    (2 * BUF_SZ)
#define OFF_B2    (3 * BUF_SZ)                   // dedicated conv2-output buffer
#define OFF_W     (4 * BUF_SZ)                   // 130048 (3 resident slabs x 24576B)
#define OFF_BIAS  (OFF_W + 73728)                // 203776 (3 x 64 floats)
#define OFF_IDXG0 (OFF_BIAS + 768)               // 254 ints, padded 1024
#define OFF_IDXG1 (OFF_IDXG0 + 1024)
#define OFF_IDXS0 (OFF_IDXG1 + 1024)             // 248 ints, padded 1024
#define OFF_IDXS1 (OFF_IDXS0 + 1024)
#define OFF_TM    (OFF_IDXS1 + 1024)
#define OFF_MBAR  (OFF_TM + 16)                  // 4 mbarriers: A0,A1,B0,B1 (8B each)
#define OFF_WORK  (OFF_MBAR + 32)
#define SMEM_BYTES (OFF_WORK + 16)               // 208704 (< 232448 max)

// idesc kind::f16: D=f32(1<<4), A=B=FP16(0), N=64 (8<<17), M=128 (8<<24)
#define IDESC_F16 0x08100010u

// Device scratch
__device__ __half g_mid[(size_t)NBATCH * NPTS * CH];   // inter-block activations, fp16
__device__ __half g_wh[NBLK * 3 * 3 * 8 * 64 * 8];     // [bl(6)][tap][kc8][o64][i%8], BN-folded fp16
__device__ float  g_bias[NBLK * 3 * CH];
__device__ int    g_comp[NBATCH * NPTS];               // composed scatter idx for block 1
__device__ int    g_ctr[2];                            // work-stealing counters
__device__ int    g_is64;

__device__ __forceinline__ uint32_t smem_u32(const void* p) {
    uint32_t a;
    asm("{ .reg .u64 t; cvta.to.shared.u64 t, %1; cvt.u32.u64 %0, t; }" : "=r"(a) : "l"(p));
    return a;
}

// cp.async 16B with zero-fill when invalid (src-size 0)
__device__ __forceinline__ void cp16(uint32_t dst, const void* src, int valid) {
    int sz = valid ? 16 : 0;
    asm volatile("cp.async.cg.shared.global [%0], [%1], 16, %2;" :: "r"(dst), "l"(src), "r"(sz) : "memory");
}
#define CP_COMMIT() asm volatile("cp.async.commit_group;" ::: "memory")
#define CP_WAIT0()  asm volatile("cp.async.wait_group 0;" ::: "memory")

__device__ __forceinline__ uint32_t packh2(float a, float b) {
    __half2 h = __floats2half2_rn(a, b);
    return *(uint32_t*)&h;
}

#if HAS_TC
// ---------------------------------------------------------------------------
__device__ __forceinline__ uint32_t elect_one() {
    uint32_t p;
    asm volatile("{\n\t.reg .pred p;\n\telect.sync _|p, 0xFFFFFFFF;\n\tselp.b32 %0, 1, 0, p;\n\t}" : "=r"(p));
    return p;
}
#define TCGEN05_ALLOC(sl, n)  asm volatile("tcgen05.alloc.cta_group::1.sync.aligned.shared::cta.b32 [%0], %1;" :: "r"(sl), "r"((uint32_t)(n)) : "memory")
#define TCGEN05_DEALLOC(t, n) asm volatile("tcgen05.dealloc.cta_group::1.sync.aligned.b32 %0, %1;" :: "r"(t), "r"((uint32_t)(n)))
#define TCGEN05_RELINQ()      asm volatile("tcgen05.relinquish_alloc_permit.cta_group::1.sync.aligned;")
#define TCGEN05_COMMIT(mb)    asm volatile("tcgen05.commit.cta_group::1.mbarrier::arrive::one.shared::cluster.b64 [%0];" :: "r"(mb) : "memory")
#define TCGEN05_WAIT_LD()     asm volatile("tcgen05.wait::ld.sync.aligned;" ::: "memory")
#define TCGEN05_FENCE_AFTER() asm volatile("tcgen05.fence::after_thread_sync;" ::: "memory")
#define TCGEN05_FENCE_BEFORE() asm volatile("tcgen05.fence::before_thread_sync;" ::: "memory")
#define FENCE_ASYNC()         asm volatile("fence.proxy.async.shared::cta;" ::: "memory")
#define MBAR_INIT(mb, n)      asm volatile("mbarrier.init.shared.b64 [%0], %1;" :: "r"(mb), "r"((uint32_t)(n)) : "memory")

#define MBAR_WAIT(mb, ph) do {                                                   \
    uint32_t _m = (mb), _p = (ph), _d;                                           \
    asm volatile("{\n\t.reg .pred p;\n\t"                                        \
        "mbarrier.try_wait.parity.acquire.cta.shared::cta.b64 p, [%1], %2;\n\t"  \
        "selp.b32 %0, 1, 0, p;\n\t}" : "=r"(_d) : "r"(_m), "r"(_p) : "memory");  \
    if (!_d) {                                                                   \
        asm volatile("{\n\t.reg .pred P1;\n\t"                                   \
        "WL_%=:\n\t"                                                             \
        "mbarrier.try_wait.parity.acquire.cta.shared::cta.b64 P1, [%0], %1, 0x989680;\n\t" \
        "@P1 bra.uni WD_%=;\n\t"                                                 \
        "bra.uni WL_%=;\n\t"                                                     \
        "WD_%=:\n\t}" :: "r"(_m), "r"(_p) : "memory");                           \
    }                                                                            \
} while (0)

#define LDTM_X32(r, addr) \
    asm volatile("tcgen05.ld.sync.aligned.32x32b.x32.b32 " \
        "{%0, %1, %2, %3, %4, %5, %6, %7, " \
        " %8, %9, %10, %11, %12, %13, %14, %15, " \
        " %16, %17, %18, %19, %20, %21, %22, %23, " \
        " %24, %25, %26, %27, %28, %29, %30, %31}, [%32];" \
        : "=r"((r)[0]),  "=r"((r)[1]),  "=r"((r)[2]),  "=r"((r)[3]), \
          "=r"((r)[4]),  "=r"((r)[5]),  "=r"((r)[6]),  "=r"((r)[7]), \
          "=r"((r)[8]),  "=r"((r)[9]),  "=r"((r)[10]), "=r"((r)[11]), \
          "=r"((r)[12]), "=r"((r)[13]), "=r"((r)[14]), "=r"((r)[15]), \
          "=r"((r)[16]), "=r"((r)[17]), "=r"((r)[18]), "=r"((r)[19]), \
          "=r"((r)[20]), "=r"((r)[21]), "=r"((r)[22]), "=r"((r)[23]), \
          "=r"((r)[24]), "=r"((r)[25]), "=r"((r)[26]), "=r"((r)[27]), \
          "=r"((r)[28]), "=r"((r)[29]), "=r"((r)[30]), "=r"((r)[31]) \
        : "r"(addr))

__device__ __forceinline__ void mma_f16(uint32_t d, uint64_t ad, uint64_t bd, uint32_t en) {
    asm volatile("{\n\t.reg .pred p;\n\tsetp.ne.u32 p, %4, 0;\n\t"
        "tcgen05.mma.cta_group::1.kind::f16 [%0], %1, %2, %3, {%5, %5, %5, %5}, p;\n\t}"
        :: "r"(d), "l"(ad), "l"(bd), "r"(IDESC_F16), "r"(en), "r"(0u) : "memory");
}

__device__ __forceinline__ uint64_t make_desc(uint32_t addr, uint32_t lbo, uint32_t sbo) {
    uint64_t d = (uint64_t)((addr >> 4) & 0x3FFF);
    d |= (uint64_t)(lbo & 0x3FFF) << 16;
    d |= (uint64_t)(sbo & 0x3FFF) << 32;
    d |= (uint64_t)1 << 46;
    return d;
}

// One conv layer (fp16, K=64 in 4 k-steps of 16); commits tile T to mbarBase+T*8.
__device__ __forceinline__ void issue_conv(uint32_t aAddr, int aLBO, uint32_t wAddr,
                                           uint32_t tmemD, uint32_t mbarBase) {
    uint64_t ab = make_desc(aAddr, aLBO, 8);
    uint64_t bb = make_desc(wAddr, 64, 8);
#pragma unroll
    for (int T = 0; T < 2; T++) {
        uint32_t en = 0;
#pragma unroll
        for (int tap = 0; tap < 3; tap++)
#pragma unroll
            for (int ks = 0; ks < 4; ks++) {
                mma_f16(tmemD + T * 64,
                        ab + (uint64_t)(T * 128 + tap + 2 * ks * aLBO),
                        bb + (uint64_t)(tap * 512 + 2 * ks * 64), en);
                en = 1;
            }
        TCGEN05_COMMIT(mbarBase + T * 8);
    }
}
#endif // HAS_TC

// ---------------------------------------------------------------------------
// Gather one tile into fp16 canonical smem. Block 1: LDG fp32 + convert + STS.
// Block 2 (linearGather): cp.async 16B from fp16 mid.
// ---------------------------------------------------------------------------
__device__ __forceinline__ void gather_tile(char* smem, uint32_t sbase, int dstOff,
                                            const float* xin32, const __half* xin16,
                                            int linearGather, int bn, int tn,
                                            const int* sG, int tid) {
    if (linearGather) {
        const __half* xb = xin16 + (size_t)bn * NPTS * CH;
        for (int it = tid; it < R_IN * 8; it += NTHREADS) {
            int r = it >> 3, c = it & 7;
            int p = tn - 3 + r;
            int valid = (p >= 0) && (p < NPTS);
            int pc = valid ? p : 0;
            cp16(sbase + dstOff + (uint32_t)(c * R_IN + r) * 16,
                 xb + (size_t)pc * CH + c * 8, valid);
        }
    } else {
        const float* xb = xin32 + (size_t)bn * NPTS * CH;
        for (int it = tid; it < R_IN * 8; it += NTHREADS) {
            int r = it >> 3, c = it & 7;
            int src = sG[r];
            uint4 u = make_uint4(0u, 0u, 0u, 0u);
            if (src >= 0) {
                const float* sp = xb + (size_t)src * CH + c * 8;
                float4 a = *(const float4*)sp;
                float4 b2 = *(const float4*)(sp + 4);
                u.x = packh2(a.x, a.y);  u.y = packh2(a.z, a.w);
                u.z = packh2(b2.x, b2.y); u.w = packh2(b2.z, b2.w);
            }
            *(uint4*)(smem + dstOff + (size_t)(c * R_IN + r) * 16) = u;
        }
    }
}

// ---------------------------------------------------------------------------
// Prep kernels
// ---------------------------------------------------------------------------
__global__ void detect_idx_kernel(const unsigned int* __restrict__ w) {
    __shared__ int any;
    if (threadIdx.x == 0) { any = 0; g_ctr[0] = 0; g_ctr[1] = 0; }
    __syncthreads();
    int local = 0;
    for (int i = threadIdx.x; i < 2048; i += blockDim.x)
        if (w[2 * i + 1] != 0u) local = 1;
    if (local) atomicOr(&any, 1);
    __syncthreads();
    if (threadIdx.x == 0) g_is64 = any ? 0 : 1;
}

// Fold BN into W; pack fp16 canonical B layout [bl][tap][kc][o][i%8].
__global__ void repack_kernel(const float* __restrict__ w,
                              const float* __restrict__ gm,
                              const float* __restrict__ bt,
                              const float* __restrict__ mn,
                              const float* __restrict__ vr) {
    int idx = blockIdx.x * blockDim.x + threadIdx.x;
    if (idx >= NBLK * 3 * CH * CH) return;
    int i  = idx & 63;
    int o  = (idx >> 6) & 63;
    int bl = idx >> 12;
    float scale = gm[bl * CH + o] * rsqrtf(vr[bl * CH + o] + 1e-5f);
#pragma unroll
    for (int t = 0; t < 3; t++) {
        float val = w[(((size_t)bl * CH + o) * CH + i) * 3 + t] * scale;
        g_wh[(size_t)bl * 12288 + t * 4096 + (i >> 3) * 512 + o * 8 + (i & 7)] = __float2half(val);
    }
    if (i == 0)
        g_bias[bl * CH + o] = bt[bl * CH + o] - mn[bl * CH + o] * scale;
}

// comp[b][p] = re2[b][ pa1[b][p] ]
__global__ void compose_kernel(const void* __restrict__ pa1, const void* __restrict__ re2) {
    int idx = blockIdx.x * blockDim.x + threadIdx.x;
    if (idx >= NBATCH * NPTS) return;
    int b = idx / NPTS;
    int is64 = g_is64;
    long long v1 = is64 ? ((const long long*)pa1)[idx] : (long long)((const int*)pa1)[idx];
    size_t j = (size_t)b * NPTS + (size_t)v1;
    int v2 = is64 ? (int)((const long long*)re2)[j] : ((const int*)re2)[j];
    g_comp[idx] = v2;
}

// ---------------------------------------------------------------------------
// Persistent fused block kernel (fp16 tcgen05), work stealing, resident weights.
// Split mbarriers A (conv1) / B (conv2+conv3). Dedicated B2 buffer removes the
// last cross-tile wait; epi3 residual preloaded into registers during phase 2.
// ---------------------------------------------------------------------------
__global__ __launch_bounds__(NTHREADS, 1)
void block_kernel(const float* __restrict__ xin32, const __half* __restrict__ xin16,
                  float* __restrict__ xout32, __half* __restrict__ xout16, int outHalf,
                  const void* __restrict__ gIdx, int linearGather,
                  const void* __restrict__ scIdx, int scMode,
                  const __half* __restrict__ wslabH, const float* __restrict__ bias,
                  int* __restrict__ ctr) {
    extern __shared__ char smem[];
    const int tid  = threadIdx.x;
    const int warp = tid >> 5;
    const int lane = tid & 31;
    const int is64  = g_is64;
    const int sIs64 = scMode ? is64 : 0;

    const uint32_t sbase = smem_u32(smem);
    float* sBias = (float*)(smem + OFF_BIAS);
    int*   sWrk  = (int*)(smem + OFF_WORK);

    const int inOff[2]   = {OFF_IN0, OFF_IN1};
    const int idxGOff[2] = {OFF_IDXG0, OFF_IDXG1};
    const int idxSOff[2] = {OFF_IDXS0, OFF_IDXS1};

#if HAS_TC
    const uint32_t mbarA = sbase + OFF_MBAR;        // conv1 commits (per tile)
    const uint32_t mbarB = sbase + OFF_MBAR + 16;   // conv2+conv3 commits (per tile)
    if (tid == 0) {
        MBAR_INIT(mbarA, 1);     MBAR_INIT(mbarA + 8, 1);
        MBAR_INIT(mbarB, 1);     MBAR_INIT(mbarB + 8, 1);
    }
    if (warp == 0) {
        TCGEN05_ALLOC(sbase + OFF_TM, 256);
        TCGEN05_RELINQ();
    }
#endif

    // steal first work + bias + ALL 3 weight slabs (resident)
    if (tid == 0) sWrk[0] = atomicAdd(ctr, 1);
    if (tid < 3 * CH) sBias[tid] = bias[tid];
#pragma unroll
    for (int k = 0; k < 9; k++)
        ((uint4*)(smem + OFF_W))[tid + k * NTHREADS] = ((const uint4*)wslabH)[tid + k * NTHREADS];
    __syncthreads();
    int work = sWrk[0];
    if (tid == 0) sWrk[0] = (work < NWORK) ? atomicAdd(ctr, 1) : NWORK;  // steal-ahead

    // ---- prologue: idx + gather for first work ----
    if (work < NWORK) {
        int b0 = work / GRID_X, t0 = (work % GRID_X) * TILE;
        int* sG = (int*)(smem + OFF_IDXG0);
        int* sS = (int*)(smem + OFF_IDXS0);
        if (!linearGather) {
            for (int r = tid; r < R_IN; r += NTHREADS) {
                int p = t0 - 3 + r;
                int v = -1;
                if (p >= 0 && p < NPTS) {
                    size_t gp = (size_t)b0 * NPTS + p;
                    v = is64 ? (int)((const long long*)gIdx)[gp] : ((const int*)gIdx)[gp];
                }
                sG[r] = v;
            }
        }
        for (int r = tid; r < TILE; r += NTHREADS) {
            int p = t0 + r;
            int v = 0;
            if (p < NPTS) {
                size_t gp = (size_t)b0 * NPTS + p;
                v = sIs64 ? (int)((const long long*)scIdx)[gp] : ((const int*)scIdx)[gp];
            }
            sS[r] = v;
        }
        __syncthreads();
        gather_tile(smem, sbase, OFF_IN0, xin32, xin16, linearGather, b0, t0, sG, tid);
    }
    CP_COMMIT();

#if HAS_TC
    uint32_t tmem;
    asm volatile("ld.shared.b32 %0, [%1];" : "=r"(tmem) : "r"(sbase + OFF_TM));

    CP_WAIT0();
    TCGEN05_FENCE_BEFORE();
    FENCE_ASYNC();
    __syncthreads();
    if (work < NWORK && warp == 0 && elect_one())
        issue_conv(sbase + OFF_IN0, R_IN, sbase + OFF_W, tmem, mbarA);
    int wnext = sWrk[0];

    // Warp mapping: tile = w>>3, colhalf = (w>>2)&1, subpartition = w&3
    const int mtile = warp >> 3;
    const int colh  = (warp >> 2) & 1;
    const int myrow = mtile * 128 + (warp & 3) * 32 + lane;
    const uint32_t myA = mbarA + mtile * 8;
    const uint32_t myB = mbarB + mtile * 8;

    int phA = 0, phB = 0, cur = 0, treg = 0;
    while (work < NWORK) {
        const int b     = work / GRID_X;
        const int tile0 = (work % GRID_X) * TILE;
        const int nxt   = cur ^ 1;
        char* INp = smem + inOff[cur];
        int* sG_n = (int*)(smem + idxGOff[nxt]);
        int* sS_c = (int*)(smem + idxSOff[cur]);
        int* sS_n = (int*)(smem + idxSOff[nxt]);
        const uint32_t dreg  = tmem + treg * 128;
        const uint32_t dregN = tmem + (treg ^ 1) * 128;
        const uint32_t dcol  = dreg + mtile * 64 + colh * 32;

        // ===== phase 1: conv1 in flight (pre-issued last iteration / prologue) =====
        if (wnext < NWORK) {   // next-work indices under conv1
            int bn = wnext / GRID_X, tn = (wnext % GRID_X) * TILE;
            if (!linearGather) {
                for (int r = tid; r < R_IN; r += NTHREADS) {
                    int p = tn - 3 + r;
                    int v = -1;
                    if (p >= 0 && p < NPTS) {
                        size_t gp = (size_t)bn * NPTS + p;
                        v = is64 ? (int)((const long long*)gIdx)[gp] : ((const int*)gIdx)[gp];
                    }
                    sG_n[r] = v;
                }
            }
            for (int r = tid; r < TILE; r += NTHREADS) {
                int p = tn + r;
                int v = 0;
                if (p < NPTS) {
                    size_t gp = (size_t)bn * NPTS + p;
                    v = sIs64 ? (int)((const long long*)scIdx)[gp] : ((const int*)scIdx)[gp];
                }
                sS_n[r] = v;
            }
        }

        MBAR_WAIT(myA, phA);             // conv1 (own tile) done
        phA ^= 1;
        TCGEN05_FENCE_AFTER();
        {
            uint32_t rg[32];
            LDTM_X32(rg, dcol);
            TCGEN05_WAIT_LD();
            int r = myrow, p = tile0 - 2 + r;
            if (r < R_B1) {
                bool zero = (p < 0) || (p >= NPTS);
                const float* bb = sBias + colh * 32;
#pragma unroll
                for (int k = 0; k < 4; k++) {
                    uint4 u = make_uint4(0u, 0u, 0u, 0u);
                    if (!zero) {
#pragma unroll
                        for (int t = 0; t < 4; t++) {
                            float a = fmaxf(__uint_as_float(rg[8 * k + 2 * t]) + bb[8 * k + 2 * t], 0.f);
                            float c2 = fmaxf(__uint_as_float(rg[8 * k + 2 * t + 1]) + bb[8 * k + 2 * t + 1], 0.f);
                            ((uint32_t*)&u)[t] = packh2(a, c2);
                        }
                    }
                    *(uint4*)(smem + OFF_B1 + ((size_t)(colh * 4 + k) * R_B1 + r) * 16) = u;
                }
            }
        }
        TCGEN05_FENCE_BEFORE();
        FENCE_ASYNC();
        __syncthreads();

        // ===== phase 2: conv2 (B1 -> TMEM); epilogue writes dedicated B2 =====
        if (warp == 0 && elect_one())
            issue_conv(sbase + OFF_B1, R_B1, sbase + OFF_W + 24576, dreg, mbarB);
        if (tid == 0) sWrk[0] = (wnext < NWORK) ? atomicAdd(ctr, 1) : NWORK;

        if (wnext < NWORK) {   // next-work gather under conv2
            int bn = wnext / GRID_X, tn = (wnext % GRID_X) * TILE;
            gather_tile(smem, sbase, inOff[nxt], xin32, xin16, linearGather, bn, tn, sG_n, tid);
        }
        CP_COMMIT();

        // residual preload for epi3 (IN stable all work; under conv2 shadow)
        uint4 resv[4];
        if (myrow < TILE) {
#pragma unroll
            for (int k = 0; k < 4; k++)
                resv[k] = *(const uint4*)(INp + ((size_t)(colh * 4 + k) * R_IN + (myrow + 3)) * 16);
        }

        MBAR_WAIT(myB, phB);
        phB ^= 1;
        TCGEN05_FENCE_AFTER();
        {
            uint32_t rg2[32];
            LDTM_X32(rg2, dcol);
            TCGEN05_WAIT_LD();
            int r = myrow, p = tile0 - 1 + r;
            if (r < R_B2) {
                bool zero = (p < 0) || (p >= NPTS);
                const float* bb = sBias + 64 + colh * 32;
#pragma unroll
                for (int k = 0; k < 4; k++) {
                    uint4 u = make_uint4(0u, 0u, 0u, 0u);
                    if (!zero) {
#pragma unroll
                        for (int t = 0; t < 4; t++) {
                            float a = fmaxf(__uint_as_float(rg2[8 * k + 2 * t]) + bb[8 * k + 2 * t], 0.f);
                            float c2 = fmaxf(__uint_as_float(rg2[8 * k + 2 * t + 1]) + bb[8 * k + 2 * t + 1], 0.f);
                            ((uint32_t*)&u)[t] = packh2(a, c2);
                        }
                    }
                    *(uint4*)(smem + OFF_B2 + ((size_t)(colh * 4 + k) * R_B2 + r) * 16) = u;
                }
            }
        }
        TCGEN05_FENCE_BEFORE();
        FENCE_ASYNC();
        __syncthreads();

        // ===== phase 3: conv3 (B2 -> TMEM, -> mbarB); pre-issue next conv1 (-> mbarA) =====
        if (warp == 0 && elect_one())
            issue_conv(sbase + OFF_B2, R_B2, sbase + OFF_W + 49152, dreg, mbarB);

        CP_WAIT0();                      // next gather landed
        TCGEN05_FENCE_BEFORE();
        FENCE_ASYNC();
        __syncthreads();                 // IN[nxt] visible to async proxy, all threads
        if (wnext < NWORK && warp == 0 && elect_one())
            issue_conv(sbase + inOff[nxt], R_IN, sbase + OFF_W, dregN, mbarA);

        MBAR_WAIT(myB, phB);             // own conv3 tile done
        phB ^= 1;
        TCGEN05_FENCE_AFTER();

        {   // epilogue 3 under next work's conv1 (residual already in registers)
            uint32_t rg[32];
            LDTM_X32(rg, dcol);
            TCGEN05_WAIT_LD();
            int r = myrow;
            bool go = (r < TILE) && (tile0 + r < NPTS);
            if (go) {
                int dst = sS_c[r];
                const float* bb = sBias + 128 + colh * 32;
#pragma unroll
                for (int k = 0; k < 4; k++) {
                    float y[8];
#pragma unroll
                    for (int t = 0; t < 4; t++) {
                        __half2 hh = *(__half2*)(((uint32_t*)&resv[k]) + t);
                        float2 rf = __half22float2(hh);
                        y[2 * t]     = fmaxf(rf.x + __uint_as_float(rg[8 * k + 2 * t])     + bb[8 * k + 2 * t], 0.f);
                        y[2 * t + 1] = fmaxf(rf.y + __uint_as_float(rg[8 * k + 2 * t + 1]) + bb[8 * k + 2 * t + 1], 0.f);
                    }
                    if (outHalf) {
                        uint4 u;
                        u.x = packh2(y[0], y[1]); u.y = packh2(y[2], y[3]);
                        u.z = packh2(y[4], y[5]); u.w = packh2(y[6], y[7]);
                        *(uint4*)(xout16 + ((size_t)b * NPTS + dst) * CH + (colh * 4 + k) * 8) = u;
                    } else {
                        float* op = xout32 + ((size_t)b * NPTS + dst) * CH + colh * 32 + 8 * k;
                        *(float4*)op       = make_float4(y[0], y[1], y[2], y[3]);
                        *(float4*)(op + 4) = make_float4(y[4], y[5], y[6], y[7]);
                    }
                }
            }
        }
        TCGEN05_FENCE_BEFORE();
        __syncthreads();

        work = wnext;
        wnext = sWrk[0];
        cur ^= 1;
        treg ^= 1;
    }
    if (warp == 0) TCGEN05_DEALLOC(tmem, 256);

#else // ---- scalar fp16 fallback (compute_103 JIT image only) ----
    CP_WAIT0();
    __syncthreads();
    const __half* sWh = (const __half*)(smem + OFF_W);
    for (int w2 = blockIdx.x; w2 < NWORK; w2 += gridDim.x) {
        const int b     = w2 / GRID_X;
        const int tile0 = (w2 % GRID_X) * TILE;
        int* sG = (int*)(smem + OFF_IDXG0);
        int* sS = (int*)(smem + OFF_IDXS0);
        __syncthreads();
        if (!linearGather) {
            for (int r = tid; r < R_IN; r += NTHREADS) {
                int p = tile0 - 3 + r;
                int v = -1;
                if (p >= 0 && p < NPTS) {
                    size_t gp = (size_t)b * NPTS + p;
                    v = is64 ? (int)((const long long*)gIdx)[gp] : ((const int*)gIdx)[gp];
                }
                sG[r] = v;
            }
        }
        for (int r = tid; r < TILE; r += NTHREADS) {
            int p = tile0 + r;
            int v = 0;
            if (p < NPTS) {
                size_t gp = (size_t)b * NPTS + p;
                v = sIs64 ? (int)((const long long*)scIdx)[gp] : ((const int*)scIdx)[gp];
            }
            sS[r] = v;
        }
        __syncthreads();
        for (int it = tid; it < R_IN * 8; it += NTHREADS) {
            int r = it >> 3, c = it & 7;
            uint4 u = make_uint4(0u, 0u, 0u, 0u);
            if (linearGather) {
                int p = tile0 - 3 + r;
                if (p >= 0 && p < NPTS)
                    u = *(const uint4*)(xin16 + ((size_t)b * NPTS + p) * CH + c * 8);
            } else {
                int src = sG[r];
                if (src >= 0) {
                    const float* sp = xin32 + ((size_t)b * NPTS + src) * CH + c * 8;
                    float4 a = *(const float4*)sp, b2 = *(const float4*)(sp + 4);
                    u.x = packh2(a.x, a.y);  u.y = packh2(a.z, a.w);
                    u.z = packh2(b2.x, b2.y); u.w = packh2(b2.z, b2.w);
                }
            }
            *(uint4*)(smem + OFF_IN0 + (size_t)(c * R_IN + r) * 16) = u;
        }
        __syncthreads();
        for (int layer = 0; layer < 3; layer++) {
            int offI = (layer == 0) ? OFF_IN0 : (layer == 1) ? OFF_B1 : OFF_B2;
            int rI   = (layer == 0) ? R_IN : (layer == 1) ? R_B1 : R_B2;
            int offO = (layer == 0) ? OFF_B1 : (layer == 1) ? OFF_B2 : OFF_B1;
            int rO   = (layer == 0) ? R_B1 : (layer == 1) ? R_B2 : R_B1;
            int live = (layer == 0) ? R_B1 : (layer == 1) ? R_B2 : TILE;
            int pb   = tile0 - 2 + layer;
            const __half* wl = sWh + layer * 12288;
            for (int r = tid; r < live; r += NTHREADS) {
                float acc[CH];
#pragma unroll
                for (int o = 0; o < CH; o++) acc[o] = 0.f;
                bool zero = (pb + r < 0) || (pb + r >= NPTS);
                if (!zero) {
                    for (int tap = 0; tap < 3; tap++)
                        for (int kc = 0; kc < 8; kc++) {
                            const __half* inp = (const __half*)(smem + offI + ((size_t)(kc * rI + r + tap) * 16));
                            float xv[8];
                            for (int t = 0; t < 8; t++) xv[t] = __half2float(inp[t]);
                            const __half* wp = wl + tap * 4096 + kc * 512;
                            for (int o = 0; o < CH; o++)
                                for (int t = 0; t < 8; t++)
                                    acc[o] += xv[t] * __half2float(wp[o * 8 + t]);
                        }
                }
                for (int o = 0; o < CH; o++) {
                    float v = 0.f;
                    if (!zero) {
                        v = acc[o];
                        if (layer < 2) v = fmaxf(v + sBias[layer * 64 + o], 0.f);
                    }
                    *(__half*)(smem + offO + ((size_t)((o >> 3) * rO + r) * 16) + (o & 7) * 2) = __float2half(v);
                }
            }
            __syncthreads();
        }
        for (int it = tid; it < TILE * 8; it += NTHREADS) {
            int r = it >> 3, c = it & 7;
            if (tile0 + r >= NPTS) continue;
            int dst = sS[r];
            const __half* hp = (const __half*)(smem + OFF_B1 + (size_t)(c * R_B1 + r) * 16);
            const __half* rp = (const __half*)(smem + OFF_IN0 + (size_t)(c * R_IN + r + 3) * 16);
            for (int t = 0; t < 8; t++) {
                float y = fmaxf(__half2float(rp[t]) + __half2float(hp[t]) + sBias[128 + c * 8 + t], 0.f);
                if (outHalf) xout16[((size_t)b * NPTS + dst) * CH + c * 8 + t] = __float2half(y);
                else         xout32[((size_t)b * NPTS + dst) * CH + c * 8 + t] = y;
            }
        }
        __syncthreads();
    }
#endif
}

// ---------------------------------------------------------------------------
// Launch
// ---------------------------------------------------------------------------
extern "C" void kernel_launch(void* const* d_in, const int* in_sizes, int n_in,
                              void* d_out, int out_size) {
    const float* x      = (const float*)d_in[0];
    const void*  pa1    = d_in[1];
    const void*  pa2    = d_in[3];
    const void*  re2    = d_in[4];
    const float* conv_w = (const float*)d_in[5];
    const float* gma    = (const float*)d_in[6];
    const float* bta    = (const float*)d_in[7];
    const float* mean   = (const float*)d_in[8];
    const float* var    = (const float*)d_in[9];

    __half* mid;  cudaGetSymbolAddress((void**)&mid,  g_mid);
    __half* wh;   cudaGetSymbolAddress((void**)&wh,   g_wh);
    float*  bias; cudaGetSymbolAddress((void**)&bias, g_bias);
    int*    comp; cudaGetSymbolAddress((void**)&comp, g_comp);
    int*    ctr;  cudaGetSymbolAddress((void**)&ctr,  g_ctr);

    int nsm = 148;
    cudaDeviceGetAttribute(&nsm, cudaDevAttrMultiProcessorCount, 0);

    cudaFuncSetAttribute(block_kernel, cudaFuncAttributeMaxDynamicSharedMemorySize, SMEM_BYTES);

    detect_idx_kernel<<<1, 256>>>((const unsigned int*)pa1);
    repack_kernel<<<(NBLK * 3 * CH * CH + 255) / 256, 256>>>(conv_w, gma, bta, mean, var);
    compose_kernel<<<(NBATCH * NPTS + 255) / 256, 256>>>(pa1, re2);

    // block 1: x(fp32) --(gather pa1, cvt fp16)--> conv --(scatter comp)--> mid(fp16, block2-gather order)
    block_kernel<<<nsm, NTHREADS, SMEM_BYTES>>>(x, nullptr, nullptr, mid, 1,
                                                pa1, 0, comp, 0, wh, bias, ctr);
    // block 2: mid(fp16) --(linear gather)--> conv --(scatter pa2)--> out(fp32)
    block_kernel<<<nsm, NTHREADS, SMEM_BYTES>>>(nullptr, mid, (float*)d_out, nullptr, 0,
                                                nullptr, 1, pa2, 1, wh + 36864,
                                                bias + 3 * CH, ctr + 1);
}